// round 6
// baseline (speedup 1.0000x reference)
#include <cuda_runtime.h>
#include <cuda_bf16.h>
#include <math.h>
#include <stdint.h>

#define BB 4
#define SS 1024
#define DD 1024
#define HH 16
#define DKK 64
#define BH (BB*HH)

// ---- scratch (device globals; no allocation allowed) ----
__device__ float g_bias[(2*SS-1)*HH];

__device__ __align__(16) __nv_bfloat16 g_ahi[4096*1024];     // hidden hi
__device__ __align__(16) __nv_bfloat16 g_alo[4096*1024];     // hidden lo
__device__ __align__(16) __nv_bfloat16 g_whi[4096*1024];     // Wq|Wk|Wv|Wo hi
__device__ __align__(16) __nv_bfloat16 g_wlo[4096*1024];
__device__ __align__(16) __nv_bfloat16 g_qkv_hi[3*4194304];  // q|k|v hi [t][bh][s][dk]
__device__ __align__(16) __nv_bfloat16 g_qkv_lo[3*4194304];
__device__ __align__(16) __nv_bfloat16 g_ctx_hi[4096*1024];  // ctx [b*s][h*dk]
__device__ __align__(16) __nv_bfloat16 g_ctx_lo[4096*1024];

// ================= PTX helpers (baseline ISA only) =================
__device__ __forceinline__ uint32_t smem_u32(const void* p) {
    uint32_t a;
    asm("{ .reg .u64 t; cvta.to.shared.u64 t, %1; cvt.u32.u64 %0, t; }"
        : "=r"(a) : "l"(p));
    return a;
}

#define CP_ASYNC16(sa, ga) \
    asm volatile("cp.async.cg.shared.global [%0], [%1], 16;" \
        :: "r"(sa), "l"(ga) : "memory")
#define CP_COMMIT() asm volatile("cp.async.commit_group;" ::: "memory")
#define CP_WAIT1()  asm volatile("cp.async.wait_group 1;" ::: "memory")
#define CP_WAIT0()  asm volatile("cp.async.wait_group 0;" ::: "memory")

__device__ __forceinline__ void ldsm4(uint32_t addr, uint32_t& r0, uint32_t& r1,
                                      uint32_t& r2, uint32_t& r3) {
    asm volatile("ldmatrix.sync.aligned.m8n8.x4.shared.b16 {%0,%1,%2,%3}, [%4];"
        : "=r"(r0), "=r"(r1), "=r"(r2), "=r"(r3) : "r"(addr));
}
__device__ __forceinline__ void ldsm4t(uint32_t addr, uint32_t& r0, uint32_t& r1,
                                       uint32_t& r2, uint32_t& r3) {
    asm volatile("ldmatrix.sync.aligned.m8n8.x4.trans.shared.b16 {%0,%1,%2,%3}, [%4];"
        : "=r"(r0), "=r"(r1), "=r"(r2), "=r"(r3) : "r"(addr));
}

__device__ __forceinline__ void mma16816(float* d, const uint32_t* a,
                                         uint32_t b0, uint32_t b1) {
    asm volatile("mma.sync.aligned.m16n8k16.row.col.f32.bf16.bf16.f32 "
        "{%0,%1,%2,%3}, {%4,%5,%6,%7}, {%8,%9}, {%0,%1,%2,%3};"
        : "+f"(d[0]), "+f"(d[1]), "+f"(d[2]), "+f"(d[3])
        : "r"(a[0]), "r"(a[1]), "r"(a[2]), "r"(a[3]), "r"(b0), "r"(b1));
}

__device__ __forceinline__ void split2(float x0, float x1, uint32_t& hi, uint32_t& lo) {
    __nv_bfloat16 h0 = __float2bfloat16(x0);
    __nv_bfloat16 h1 = __float2bfloat16(x1);
    __nv_bfloat162 th; th.x = h0; th.y = h1;
    hi = *(uint32_t*)&th;
    __nv_bfloat162 tl;
    tl.x = __float2bfloat16(x0 - __bfloat162float(h0));
    tl.y = __float2bfloat16(x1 - __bfloat162float(h1));
    lo = *(uint32_t*)&tl;
}

// ------------------------------------------------------------------
__global__ void split_kernel(const float* __restrict__ x,
                             __nv_bfloat16* __restrict__ hi,
                             __nv_bfloat16* __restrict__ lo, int n) {
    int i = blockIdx.x * blockDim.x + threadIdx.x;
    if (i >= n) return;
    float v = x[i];
    __nv_bfloat16 h = __float2bfloat16(v);
    hi[i] = h;
    lo[i] = __float2bfloat16(v - __bfloat162float(h));
}

// all four weights in one launch: dst rows t*1M..
__global__ void split4_kernel(const float* __restrict__ w0, const float* __restrict__ w1,
                              const float* __restrict__ w2, const float* __restrict__ w3,
                              __nv_bfloat16* __restrict__ hi,
                              __nv_bfloat16* __restrict__ lo) {
    int i = blockIdx.x * blockDim.x + threadIdx.x;   // 0..4M-1
    int t = i >> 20;
    int off = i & 1048575;
    const float* src = (t == 0) ? w0 : (t == 1) ? w1 : (t == 2) ? w2 : w3;
    float v = src[off];
    __nv_bfloat16 h = __float2bfloat16(v);
    hi[i] = h;
    lo[i] = __float2bfloat16(v - __bfloat162float(h));
}

// ------------------------------------------------------------------
__global__ void bias_kernel(const float* __restrict__ rel_bias) {
    int idx = blockIdx.x * blockDim.x + threadIdx.x;
    const int total = (2*SS-1)*HH;
    if (idx >= total) return;
    int d = idx / HH;
    int h = idx - d*HH;
    int rp = d - (SS - 1);
    int rb = (rp > 0) ? 16 : 0;
    int n = rp < 0 ? -rp : rp;
    int b;
    if (n < 8) {
        b = n;
    } else {
        double v = log((double)n / 8.0) / log(16.0) * 8.0;
        int large = 8 + (int)v;
        b = large < 15 ? large : 15;
    }
    g_bias[idx] = rel_bias[(rb + b)*HH + h];
}

// ------------------------------------------------------------------
// HMMA bf16x3 GEMM (as round 5)
// ------------------------------------------------------------------
#define BKG 32
#define STAGES 3
#define TENSOR_BYTES (128*64)
#define STAGE_BYTES  (4*TENSOR_BYTES)
#define GEMM_SMEM    (STAGES*STAGE_BYTES)

__global__ void __launch_bounds__(256, 2) gemm_mma_kernel(
    const __nv_bfloat16* __restrict__ Ahi, const __nv_bfloat16* __restrict__ Alo,
    const __nv_bfloat16* __restrict__ Whi, const __nv_bfloat16* __restrict__ Wlo,
    float* __restrict__ C,
    __nv_bfloat16* __restrict__ Chi, __nv_bfloat16* __restrict__ Clo,
    int mode)
{
    extern __shared__ __align__(128) char smem[];
    const uint32_t sb = smem_u32(smem);
    const int tid  = threadIdx.x;
    const int warp = tid >> 5, lane = tid & 31;
    const int wm = warp >> 2, wn = warp & 3;
    const int nt = blockIdx.x, mt = blockIdx.y;

    const __nv_bfloat16* src0 = Ahi + (size_t)(mt*128)*1024;
    const __nv_bfloat16* src1 = Alo + (size_t)(mt*128)*1024;
    const __nv_bfloat16* src2 = Whi + (size_t)(nt*128)*1024;
    const __nv_bfloat16* src3 = Wlo + (size_t)(nt*128)*1024;
    const __nv_bfloat16* mysrc = (tid < 64) ? src0 : (tid < 128) ? src1
                               : (tid < 192) ? src2 : src3;
    const int t4 = tid >> 6;
    const int li = tid & 63;

    #define ISSUE(it) do { \
        int _stg = (it) % STAGES; \
        uint32_t _sbase = sb + _stg*STAGE_BYTES + t4*TENSOR_BYTES; \
        const __nv_bfloat16* _g = mysrc + (it)*BKG; \
        _Pragma("unroll") \
        for (int _j = 0; _j < 8; _j++) { \
            int _ch = li + _j*64; \
            int _r = _ch >> 2, _c = _ch & 3; \
            int _cs = _c ^ ((_r >> 1) & 3); \
            CP_ASYNC16(_sbase + _r*64 + _cs*16, _g + (size_t)_r*1024 + _c*8); \
        } \
    } while (0)

    ISSUE(0); CP_COMMIT();
    ISSUE(1); CP_COMMIT();

    float acc[4][4][4];
    #pragma unroll
    for (int i = 0; i < 4; i++)
        #pragma unroll
        for (int j = 0; j < 4; j++)
            #pragma unroll
            for (int q = 0; q < 4; q++) acc[i][j][q] = 0.f;

    const int arow = lane & 15;
    const int asel = lane >> 4;
    const int brow = ((lane >> 4) << 3) | (lane & 7);
    const int bsel = (lane >> 3) & 1;

    for (int it = 0; it < 32; it++) {
        CP_WAIT1();
        __syncthreads();
        if (it + 2 < 32) ISSUE(it + 2);
        CP_COMMIT();

        const uint32_t st = sb + (it % STAGES)*STAGE_BYTES;
        #pragma unroll
        for (int ks = 0; ks < 2; ks++) {
            uint32_t ah[4][4], al[4][4];
            #pragma unroll
            for (int mi = 0; mi < 4; mi++) {
                int r = wm*64 + mi*16 + arow;
                int c = 2*ks + asel;
                uint32_t off = (uint32_t)(r*64 + ((c ^ ((r>>1)&3))*16));
                ldsm4(st + off,               ah[mi][0], ah[mi][1], ah[mi][2], ah[mi][3]);
                ldsm4(st + TENSOR_BYTES + off, al[mi][0], al[mi][1], al[mi][2], al[mi][3]);
            }
            uint32_t bh2[2][4], bl2[2][4];
            #pragma unroll
            for (int np = 0; np < 2; np++) {
                int r = wn*32 + np*16 + brow;
                int c = 2*ks + bsel;
                uint32_t off = (uint32_t)(r*64 + ((c ^ ((r>>1)&3))*16));
                ldsm4(st + 2*TENSOR_BYTES + off, bh2[np][0], bh2[np][1], bh2[np][2], bh2[np][3]);
                ldsm4(st + 3*TENSOR_BYTES + off, bl2[np][0], bl2[np][1], bl2[np][2], bl2[np][3]);
            }
            #pragma unroll
            for (int mi = 0; mi < 4; mi++)
                #pragma unroll
                for (int ni = 0; ni < 4; ni++) {
                    uint32_t b0h = bh2[ni>>1][(ni&1)*2], b1h = bh2[ni>>1][(ni&1)*2+1];
                    uint32_t b0l = bl2[ni>>1][(ni&1)*2], b1l = bl2[ni>>1][(ni&1)*2+1];
                    mma16816(acc[mi][ni], ah[mi], b0h, b1h);
                    mma16816(acc[mi][ni], ah[mi], b0l, b1l);
                    mma16816(acc[mi][ni], al[mi], b0h, b1h);
                }
        }
    }
    #undef ISSUE

    const int lrow = lane >> 2;
    const int lcol = (lane & 3)*2;
    if (mode == 0) {
        const int mrow0 = mt*128 + wm*64;
        const int ncol0 = nt*128 + wn*32;
        #pragma unroll
        for (int mi = 0; mi < 4; mi++)
            #pragma unroll
            for (int ni = 0; ni < 4; ni++) {
                int m0 = mrow0 + mi*16 + lrow;
                int n0 = ncol0 + ni*8 + lcol;
                *(float2*)(C + (size_t)m0*1024 + n0) =
                    make_float2(acc[mi][ni][0], acc[mi][ni][1]);
                *(float2*)(C + (size_t)(m0+8)*1024 + n0) =
                    make_float2(acc[mi][ni][2], acc[mi][ni][3]);
            }
    } else {
        const int t = nt >> 3;
        const size_t tbase = (size_t)t * 4194304;
        const int mrow0 = mt*128 + wm*64;
        const int ncol0 = (nt & 7)*128 + wn*32;
        #pragma unroll
        for (int mi = 0; mi < 4; mi++)
            #pragma unroll
            for (int ni = 0; ni < 4; ni++) {
                int m0 = mrow0 + mi*16 + lrow;
                int m1 = m0 + 8;
                int n0 = ncol0 + ni*8 + lcol;
                int h = n0 >> 6, dk = n0 & 63;
                int b0 = m0 >> 10, s0 = m0 & 1023;
                int b1 = m1 >> 10, s1 = m1 & 1023;
                size_t i0 = tbase + ((size_t)((b0*HH + h)*SS + s0))*DKK + dk;
                size_t i1 = tbase + ((size_t)((b1*HH + h)*SS + s1))*DKK + dk;
                uint32_t hi, lo;
                split2(acc[mi][ni][0], acc[mi][ni][1], hi, lo);
                *(uint32_t*)&Chi[i0] = hi;
                *(uint32_t*)&Clo[i0] = lo;
                split2(acc[mi][ni][2], acc[mi][ni][3], hi, lo);
                *(uint32_t*)&Chi[i1] = hi;
                *(uint32_t*)&Clo[i1] = lo;
            }
    }
}

// ------------------------------------------------------------------
// Fused flash attention. KV tile = 64 rows, 16 iters, 2-stage pipeline.
// smem: Q 32K + 2 stages x 32K + bias 1K = 97K -> 2 CTAs/SM.
// ------------------------------------------------------------------
#define T16 16384
#define T8  8192
#define FS_QH 0
#define FS_QL T16
#define FS_ST0 (2*T16)
#define FS_ST1 (2*T16 + 4*T8)
#define FS_BIAS (2*T16 + 8*T8)
#define FLASH_SMEM (2*T16 + 8*T8 + 1024)

#define SWZ(r, c) ((uint32_t)((r)*128 + (((c) ^ ((r)&7))*16)))

__global__ void __launch_bounds__(256, 2) flash_kernel() {
    extern __shared__ __align__(128) char smem[];
    const uint32_t sb = smem_u32(smem);
    float* bias_s = (float*)(smem + FS_BIAS);

    const int tid  = threadIdx.x;
    const int w = tid >> 5, lane = tid & 31;
    const int mbase = blockIdx.x * 128;
    const int bh = blockIdx.y;
    const int b = bh >> 4, h = bh & 15;

    const size_t base = (size_t)bh*SS*DKK;
    const __nv_bfloat16* Qh = g_qkv_hi + base + (size_t)mbase*DKK;
    const __nv_bfloat16* Ql = g_qkv_lo + base + (size_t)mbase*DKK;
    const __nv_bfloat16* Kh = g_qkv_hi + 4194304 + base;
    const __nv_bfloat16* Kl = g_qkv_lo + 4194304 + base;
    const __nv_bfloat16* Vh = g_qkv_hi + 8388608 + base;
    const __nv_bfloat16* Vl = g_qkv_lo + 8388608 + base;

    // prologue: Q (group with KV0)
    #pragma unroll
    for (int i = 0; i < 4; i++) {
        int id = tid + i*256;
        int r = id >> 3, c = id & 7;
        uint32_t off = SWZ(r, c);
        const size_t go = (size_t)r*64 + c*8;
        CP_ASYNC16(sb + FS_QH + off, Qh + go);
        CP_ASYNC16(sb + FS_QL + off, Ql + go);
    }
    // KV stage issue: 64 rows x 8 chunks = 512 chunks per tensor
    #define ISSUE_KV(j, stoff) do { \
        const size_t _jo = (size_t)(j)*64*64; \
        _Pragma("unroll") \
        for (int _i = 0; _i < 2; _i++) { \
            int _id = tid + _i*256; \
            int _r = _id >> 3, _c = _id & 7; \
            uint32_t _off = SWZ(_r, _c); \
            const size_t _go = _jo + (size_t)_r*64 + _c*8; \
            CP_ASYNC16(sb + (stoff) + 0*T8 + _off, Kh + _go); \
            CP_ASYNC16(sb + (stoff) + 1*T8 + _off, Kl + _go); \
            CP_ASYNC16(sb + (stoff) + 2*T8 + _off, Vh + _go); \
            CP_ASYNC16(sb + (stoff) + 3*T8 + _off, Vl + _go); \
        } \
    } while (0)
    ISSUE_KV(0, FS_ST0); CP_COMMIT();
    ISSUE_KV(1, FS_ST1); CP_COMMIT();

    float Oacc[8][4];
    #pragma unroll
    for (int d = 0; d < 8; d++)
        #pragma unroll
        for (int q = 0; q < 4; q++) Oacc[d][q] = 0.f;
    float mrun0 = -1e30f, mrun1 = -1e30f, lrun0 = 0.f, lrun1 = 0.f;

    const int r0 = lane >> 2;
    const int colb = (lane & 3)*2;
    const int rl0 = w*16 + r0;
    const int rl1 = rl0 + 8;

    const int a_r = w*16 + (lane & 15);
    const int a_s = lane >> 4;
    const int b_r = ((lane >> 4) << 3) | (lane & 7);
    const int b_s = (lane >> 3) & 1;
    const int v_k = ((lane >> 3) & 1)*8 + (lane & 7);
    const int v_c = lane >> 4;

    for (int j = 0; j < 16; j++) {
        if (j < 15) { CP_WAIT1(); } else { CP_WAIT0(); }
        __syncthreads();
        if (tid < 191) {
            int delta = j*64 - mbase + (tid - 127);
            bias_s[tid] = g_bias[(size_t)(delta + SS - 1)*HH + h];
        }
        __syncthreads();

        const uint32_t st = sb + ((j & 1) ? FS_ST1 : FS_ST0);

        // ---- S = Q K^T (bf16x3): 128x64 ----
        float sacc[8][4];
        #pragma unroll
        for (int nt = 0; nt < 8; nt++)
            #pragma unroll
            for (int q = 0; q < 4; q++) sacc[nt][q] = 0.f;

        #pragma unroll
        for (int ks = 0; ks < 4; ks++) {
            uint32_t aqh[4], aql[4];
            uint32_t aoff = SWZ(a_r, 2*ks + a_s);
            ldsm4(sb + FS_QH + aoff, aqh[0], aqh[1], aqh[2], aqh[3]);
            ldsm4(sb + FS_QL + aoff, aql[0], aql[1], aql[2], aql[3]);
            #pragma unroll
            for (int np = 0; np < 4; np++) {
                uint32_t kh[4], kl[4];
                uint32_t boff = SWZ(np*16 + b_r, 2*ks + b_s);
                ldsm4(st + 0*T8 + boff, kh[0], kh[1], kh[2], kh[3]);
                ldsm4(st + 1*T8 + boff, kl[0], kl[1], kl[2], kl[3]);
                mma16816(sacc[2*np],   aqh, kh[0], kh[1]);
                mma16816(sacc[2*np],   aqh, kl[0], kl[1]);
                mma16816(sacc[2*np],   aql, kh[0], kh[1]);
                mma16816(sacc[2*np+1], aqh, kh[2], kh[3]);
                mma16816(sacc[2*np+1], aqh, kl[2], kl[3]);
                mma16816(sacc[2*np+1], aql, kh[2], kh[3]);
            }
        }

        // ---- bias ----
        #pragma unroll
        for (int nt = 0; nt < 8; nt++) {
            int col = nt*8 + colb;
            sacc[nt][0] += bias_s[col     - rl0 + 127];
            sacc[nt][1] += bias_s[col + 1 - rl0 + 127];
            sacc[nt][2] += bias_s[col     - rl1 + 127];
            sacc[nt][3] += bias_s[col + 1 - rl1 + 127];
        }

        // ---- online softmax ----
        float mx0 = -1e30f, mx1 = -1e30f;
        #pragma unroll
        for (int nt = 0; nt < 8; nt++) {
            mx0 = fmaxf(mx0, fmaxf(sacc[nt][0], sacc[nt][1]));
            mx1 = fmaxf(mx1, fmaxf(sacc[nt][2], sacc[nt][3]));
        }
        mx0 = fmaxf(mx0, __shfl_xor_sync(0xffffffffu, mx0, 1));
        mx0 = fmaxf(mx0, __shfl_xor_sync(0xffffffffu, mx0, 2));
        mx1 = fmaxf(mx1, __shfl_xor_sync(0xffffffffu, mx1, 1));
        mx1 = fmaxf(mx1, __shfl_xor_sync(0xffffffffu, mx1, 2));

        float mn0 = fmaxf(mrun0, mx0);
        float mn1 = fmaxf(mrun1, mx1);
        float al0 = __expf(mrun0 - mn0);
        float al1 = __expf(mrun1 - mn1);
        mrun0 = mn0; mrun1 = mn1;

        float rs0 = 0.f, rs1 = 0.f;
        #pragma unroll
        for (int nt = 0; nt < 8; nt++) {
            sacc[nt][0] = __expf(sacc[nt][0] - mn0);
            sacc[nt][1] = __expf(sacc[nt][1] - mn0);
            sacc[nt][2] = __expf(sacc[nt][2] - mn1);
            sacc[nt][3] = __expf(sacc[nt][3] - mn1);
            rs0 += sacc[nt][0] + sacc[nt][1];
            rs1 += sacc[nt][2] + sacc[nt][3];
        }
        rs0 += __shfl_xor_sync(0xffffffffu, rs0, 1);
        rs0 += __shfl_xor_sync(0xffffffffu, rs0, 2);
        rs1 += __shfl_xor_sync(0xffffffffu, rs1, 1);
        rs1 += __shfl_xor_sync(0xffffffffu, rs1, 2);
        lrun0 = lrun0*al0 + rs0;
        lrun1 = lrun1*al1 + rs1;

        #pragma unroll
        for (int d = 0; d < 8; d++) {
            Oacc[d][0] *= al0; Oacc[d][1] *= al0;
            Oacc[d][2] *= al1; Oacc[d][3] *= al1;
        }

        // ---- O += P V (bf16x3) ----
        #pragma unroll
        for (int ks = 0; ks < 4; ks++) {
            uint32_t ph[4], pl[4];
            split2(sacc[2*ks][0],   sacc[2*ks][1],   ph[0], pl[0]);
            split2(sacc[2*ks][2],   sacc[2*ks][3],   ph[1], pl[1]);
            split2(sacc[2*ks+1][0], sacc[2*ks+1][1], ph[2], pl[2]);
            split2(sacc[2*ks+1][2], sacc[2*ks+1][3], ph[3], pl[3]);
            #pragma unroll
            for (int dp = 0; dp < 4; dp++) {
                uint32_t vh[4], vl[4];
                uint32_t voff = SWZ(ks*16 + v_k, dp*2 + v_c);
                ldsm4t(st + 2*T8 + voff, vh[0], vh[1], vh[2], vh[3]);
                ldsm4t(st + 3*T8 + voff, vl[0], vl[1], vl[2], vl[3]);
                mma16816(Oacc[2*dp],   ph, vh[0], vh[1]);
                mma16816(Oacc[2*dp],   ph, vl[0], vl[1]);
                mma16816(Oacc[2*dp],   pl, vh[0], vh[1]);
                mma16816(Oacc[2*dp+1], ph, vh[2], vh[3]);
                mma16816(Oacc[2*dp+1], ph, vl[2], vl[3]);
                mma16816(Oacc[2*dp+1], pl, vh[2], vh[3]);
            }
        }

        __syncthreads();   // all warps done reading stage j&1
        if (j + 2 < 16) {
            ISSUE_KV(j + 2, ((j & 1) ? FS_ST1 : FS_ST0));
            CP_COMMIT();
        }
    }
    #undef ISSUE_KV

    // ---- epilogue: normalize + write ctx as bf16 hi/lo ----
    float inv0 = 1.0f / lrun0;
    float inv1 = 1.0f / lrun1;
    int m0 = mbase + rl0;
    int m1 = mbase + rl1;
    #pragma unroll
    for (int dt = 0; dt < 8; dt++) {
        int d = dt*8 + colb;
        size_t i0 = ((size_t)(b*SS + m0))*DD + h*DKK + d;
        size_t i1 = ((size_t)(b*SS + m1))*DD + h*DKK + d;
        uint32_t hi, lo;
        split2(Oacc[dt][0]*inv0, Oacc[dt][1]*inv0, hi, lo);
        *(uint32_t*)&g_ctx_hi[i0] = hi;
        *(uint32_t*)&g_ctx_lo[i0] = lo;
        split2(Oacc[dt][2]*inv1, Oacc[dt][3]*inv1, hi, lo);
        *(uint32_t*)&g_ctx_hi[i1] = hi;
        *(uint32_t*)&g_ctx_lo[i1] = lo;
    }
}

// ------------------------------------------------------------------
extern "C" void kernel_launch(void* const* d_in, const int* in_sizes, int n_in,
                              void* d_out, int out_size) {
    const float* hidden   = (const float*)d_in[0];
    const float* Wq       = (const float*)d_in[1];
    const float* Wk       = (const float*)d_in[2];
    const float* Wv       = (const float*)d_in[3];
    const float* Wo       = (const float*)d_in[4];
    const float* rel_bias = (const float*)d_in[5];
    float* out = (float*)d_out;

    __nv_bfloat16 *pahi, *palo, *pwhi, *pwlo, *pqkvh, *pqkvl, *pchi, *pclo;
    cudaGetSymbolAddress((void**)&pahi, g_ahi);
    cudaGetSymbolAddress((void**)&palo, g_alo);
    cudaGetSymbolAddress((void**)&pwhi, g_whi);
    cudaGetSymbolAddress((void**)&pwlo, g_wlo);
    cudaGetSymbolAddress((void**)&pqkvh, g_qkv_hi);
    cudaGetSymbolAddress((void**)&pqkvl, g_qkv_lo);
    cudaGetSymbolAddress((void**)&pchi, g_ctx_hi);
    cudaGetSymbolAddress((void**)&pclo, g_ctx_lo);

    cudaFuncSetAttribute(gemm_mma_kernel,
                         cudaFuncAttributeMaxDynamicSharedMemorySize, GEMM_SMEM);
    cudaFuncSetAttribute(flash_kernel,
                         cudaFuncAttributeMaxDynamicSharedMemorySize, FLASH_SMEM);

    const int nA = 4096*1024;

    bias_kernel<<<((2*SS-1)*HH + 255)/256, 256>>>(rel_bias);
    split_kernel<<<(nA + 255)/256, 256>>>(hidden, pahi, palo, nA);
    split4_kernel<<<(4194304 + 255)/256, 256>>>(Wq, Wk, Wv, Wo, pwhi, pwlo);

    // fused QKV projection -> bf16 hi/lo head-split
    gemm_mma_kernel<<<dim3(24, 32), 256, GEMM_SMEM>>>(
        pahi, palo, pwhi, pwlo, nullptr, pqkvh, pqkvl, 2);

    // fused attention (2 CTAs/SM)
    flash_kernel<<<dim3(8, BH), 256, FLASH_SMEM>>>();

    // output projection (fp32 out)
    gemm_mma_kernel<<<dim3(8, 32), 256, GEMM_SMEM>>>(
        pchi, pclo, pwhi + 3145728, pwlo + 3145728, out, nullptr, nullptr, 0);
}

// round 8
// speedup vs baseline: 1.5327x; 1.5327x over previous
#include <cuda_runtime.h>
#include <cuda_bf16.h>
#include <math.h>
#include <stdint.h>

#define BB 4
#define SS 1024
#define DD 1024
#define HH 16
#define DKK 64
#define BH (BB*HH)

// ---- scratch (device globals; no allocation allowed) ----
__device__ float g_bias[(2*SS-1)*HH];

__device__ __align__(16) __nv_bfloat16 g_ahi[4096*1024];     // hidden hi
__device__ __align__(16) __nv_bfloat16 g_alo[4096*1024];     // hidden lo
__device__ __align__(16) __nv_bfloat16 g_whi[4096*1024];     // Wq|Wk|Wv|Wo hi
__device__ __align__(16) __nv_bfloat16 g_wlo[4096*1024];
__device__ __align__(16) __nv_bfloat16 g_qkv_hi[3*4194304];  // q|k|v hi [t][bh][s][dk]
__device__ __align__(16) __nv_bfloat16 g_qkv_lo[3*4194304];
__device__ __align__(16) __nv_bfloat16 g_ctx_hi[4096*1024];  // ctx [b*s][h*dk]
__device__ __align__(16) __nv_bfloat16 g_ctx_lo[4096*1024];

// ================= PTX helpers (baseline ISA only) =================
__device__ __forceinline__ uint32_t smem_u32(const void* p) {
    uint32_t a;
    asm("{ .reg .u64 t; cvta.to.shared.u64 t, %1; cvt.u32.u64 %0, t; }"
        : "=r"(a) : "l"(p));
    return a;
}

#define CP_ASYNC16(sa, ga) \
    asm volatile("cp.async.cg.shared.global [%0], [%1], 16;" \
        :: "r"(sa), "l"(ga) : "memory")
#define CP_COMMIT() asm volatile("cp.async.commit_group;" ::: "memory")
#define CP_WAIT1()  asm volatile("cp.async.wait_group 1;" ::: "memory")
#define CP_WAIT0()  asm volatile("cp.async.wait_group 0;" ::: "memory")

__device__ __forceinline__ void ldsm4(uint32_t addr, uint32_t& r0, uint32_t& r1,
                                      uint32_t& r2, uint32_t& r3) {
    asm volatile("ldmatrix.sync.aligned.m8n8.x4.shared.b16 {%0,%1,%2,%3}, [%4];"
        : "=r"(r0), "=r"(r1), "=r"(r2), "=r"(r3) : "r"(addr));
}
__device__ __forceinline__ void ldsm4t(uint32_t addr, uint32_t& r0, uint32_t& r1,
                                       uint32_t& r2, uint32_t& r3) {
    asm volatile("ldmatrix.sync.aligned.m8n8.x4.trans.shared.b16 {%0,%1,%2,%3}, [%4];"
        : "=r"(r0), "=r"(r1), "=r"(r2), "=r"(r3) : "r"(addr));
}

__device__ __forceinline__ void mma16816(float* d, const uint32_t* a,
                                         uint32_t b0, uint32_t b1) {
    asm volatile("mma.sync.aligned.m16n8k16.row.col.f32.bf16.bf16.f32 "
        "{%0,%1,%2,%3}, {%4,%5,%6,%7}, {%8,%9}, {%0,%1,%2,%3};"
        : "+f"(d[0]), "+f"(d[1]), "+f"(d[2]), "+f"(d[3])
        : "r"(a[0]), "r"(a[1]), "r"(a[2]), "r"(a[3]), "r"(b0), "r"(b1));
}

__device__ __forceinline__ void split2(float x0, float x1, uint32_t& hi, uint32_t& lo) {
    __nv_bfloat16 h0 = __float2bfloat16(x0);
    __nv_bfloat16 h1 = __float2bfloat16(x1);
    __nv_bfloat162 th; th.x = h0; th.y = h1;
    hi = *(uint32_t*)&th;
    __nv_bfloat162 tl;
    tl.x = __float2bfloat16(x0 - __bfloat162float(h0));
    tl.y = __float2bfloat16(x1 - __bfloat162float(h1));
    lo = *(uint32_t*)&tl;
}

// ------------------------------------------------------------------
__global__ void split_kernel(const float* __restrict__ x,
                             __nv_bfloat16* __restrict__ hi,
                             __nv_bfloat16* __restrict__ lo, int n) {
    int i = blockIdx.x * blockDim.x + threadIdx.x;
    if (i >= n) return;
    float v = x[i];
    __nv_bfloat16 h = __float2bfloat16(v);
    hi[i] = h;
    lo[i] = __float2bfloat16(v - __bfloat162float(h));
}

__global__ void split4_kernel(const float* __restrict__ w0, const float* __restrict__ w1,
                              const float* __restrict__ w2, const float* __restrict__ w3,
                              __nv_bfloat16* __restrict__ hi,
                              __nv_bfloat16* __restrict__ lo) {
    int i = blockIdx.x * blockDim.x + threadIdx.x;   // 0..4M-1
    int t = i >> 20;
    int off = i & 1048575;
    const float* src = (t == 0) ? w0 : (t == 1) ? w1 : (t == 2) ? w2 : w3;
    float v = src[off];
    __nv_bfloat16 h = __float2bfloat16(v);
    hi[i] = h;
    lo[i] = __float2bfloat16(v - __bfloat162float(h));
}

// ------------------------------------------------------------------
__global__ void bias_kernel(const float* __restrict__ rel_bias) {
    int idx = blockIdx.x * blockDim.x + threadIdx.x;
    const int total = (2*SS-1)*HH;
    if (idx >= total) return;
    int d = idx / HH;
    int h = idx - d*HH;
    int rp = d - (SS - 1);
    int rb = (rp > 0) ? 16 : 0;
    int n = rp < 0 ? -rp : rp;
    int b;
    if (n < 8) {
        b = n;
    } else {
        double v = log((double)n / 8.0) / log(16.0) * 8.0;
        int large = 8 + (int)v;
        b = large < 15 ? large : 15;
    }
    g_bias[idx] = rel_bias[(rb + b)*HH + h];
}

// ------------------------------------------------------------------
// HMMA bf16x3 GEMM (unchanged)
// ------------------------------------------------------------------
#define BKG 32
#define STAGES 3
#define TENSOR_BYTES (128*64)
#define STAGE_BYTES  (4*TENSOR_BYTES)
#define GEMM_SMEM    (STAGES*STAGE_BYTES)

__global__ void __launch_bounds__(256, 2) gemm_mma_kernel(
    const __nv_bfloat16* __restrict__ Ahi, const __nv_bfloat16* __restrict__ Alo,
    const __nv_bfloat16* __restrict__ Whi, const __nv_bfloat16* __restrict__ Wlo,
    float* __restrict__ C,
    __nv_bfloat16* __restrict__ Chi, __nv_bfloat16* __restrict__ Clo,
    int mode)
{
    extern __shared__ __align__(128) char smem[];
    const uint32_t sb = smem_u32(smem);
    const int tid  = threadIdx.x;
    const int warp = tid >> 5, lane = tid & 31;
    const int wm = warp >> 2, wn = warp & 3;
    const int nt = blockIdx.x, mt = blockIdx.y;

    const __nv_bfloat16* src0 = Ahi + (size_t)(mt*128)*1024;
    const __nv_bfloat16* src1 = Alo + (size_t)(mt*128)*1024;
    const __nv_bfloat16* src2 = Whi + (size_t)(nt*128)*1024;
    const __nv_bfloat16* src3 = Wlo + (size_t)(nt*128)*1024;
    const __nv_bfloat16* mysrc = (tid < 64) ? src0 : (tid < 128) ? src1
                               : (tid < 192) ? src2 : src3;
    const int t4 = tid >> 6;
    const int li = tid & 63;

    #define ISSUE(it) do { \
        int _stg = (it) % STAGES; \
        uint32_t _sbase = sb + _stg*STAGE_BYTES + t4*TENSOR_BYTES; \
        const __nv_bfloat16* _g = mysrc + (it)*BKG; \
        _Pragma("unroll") \
        for (int _j = 0; _j < 8; _j++) { \
            int _ch = li + _j*64; \
            int _r = _ch >> 2, _c = _ch & 3; \
            int _cs = _c ^ ((_r >> 1) & 3); \
            CP_ASYNC16(_sbase + _r*64 + _cs*16, _g + (size_t)_r*1024 + _c*8); \
        } \
    } while (0)

    ISSUE(0); CP_COMMIT();
    ISSUE(1); CP_COMMIT();

    float acc[4][4][4];
    #pragma unroll
    for (int i = 0; i < 4; i++)
        #pragma unroll
        for (int j = 0; j < 4; j++)
            #pragma unroll
            for (int q = 0; q < 4; q++) acc[i][j][q] = 0.f;

    const int arow = lane & 15;
    const int asel = lane >> 4;
    const int brow = ((lane >> 4) << 3) | (lane & 7);
    const int bsel = (lane >> 3) & 1;

    for (int it = 0; it < 32; it++) {
        CP_WAIT1();
        __syncthreads();
        if (it + 2 < 32) ISSUE(it + 2);
        CP_COMMIT();

        const uint32_t st = sb + (it % STAGES)*STAGE_BYTES;
        #pragma unroll
        for (int ks = 0; ks < 2; ks++) {
            uint32_t ah[4][4], al[4][4];
            #pragma unroll
            for (int mi = 0; mi < 4; mi++) {
                int r = wm*64 + mi*16 + arow;
                int c = 2*ks + asel;
                uint32_t off = (uint32_t)(r*64 + ((c ^ ((r>>1)&3))*16));
                ldsm4(st + off,               ah[mi][0], ah[mi][1], ah[mi][2], ah[mi][3]);
                ldsm4(st + TENSOR_BYTES + off, al[mi][0], al[mi][1], al[mi][2], al[mi][3]);
            }
            uint32_t bh2[2][4], bl2[2][4];
            #pragma unroll
            for (int np = 0; np < 2; np++) {
                int r = wn*32 + np*16 + brow;
                int c = 2*ks + bsel;
                uint32_t off = (uint32_t)(r*64 + ((c ^ ((r>>1)&3))*16));
                ldsm4(st + 2*TENSOR_BYTES + off, bh2[np][0], bh2[np][1], bh2[np][2], bh2[np][3]);
                ldsm4(st + 3*TENSOR_BYTES + off, bl2[np][0], bl2[np][1], bl2[np][2], bl2[np][3]);
            }
            #pragma unroll
            for (int mi = 0; mi < 4; mi++)
                #pragma unroll
                for (int ni = 0; ni < 4; ni++) {
                    uint32_t b0h = bh2[ni>>1][(ni&1)*2], b1h = bh2[ni>>1][(ni&1)*2+1];
                    uint32_t b0l = bl2[ni>>1][(ni&1)*2], b1l = bl2[ni>>1][(ni&1)*2+1];
                    mma16816(acc[mi][ni], ah[mi], b0h, b1h);
                    mma16816(acc[mi][ni], ah[mi], b0l, b1l);
                    mma16816(acc[mi][ni], al[mi], b0h, b1h);
                }
        }
    }
    #undef ISSUE

    const int lrow = lane >> 2;
    const int lcol = (lane & 3)*2;
    if (mode == 0) {
        const int mrow0 = mt*128 + wm*64;
        const int ncol0 = nt*128 + wn*32;
        #pragma unroll
        for (int mi = 0; mi < 4; mi++)
            #pragma unroll
            for (int ni = 0; ni < 4; ni++) {
                int m0 = mrow0 + mi*16 + lrow;
                int n0 = ncol0 + ni*8 + lcol;
                *(float2*)(C + (size_t)m0*1024 + n0) =
                    make_float2(acc[mi][ni][0], acc[mi][ni][1]);
                *(float2*)(C + (size_t)(m0+8)*1024 + n0) =
                    make_float2(acc[mi][ni][2], acc[mi][ni][3]);
            }
    } else {
        const int t = nt >> 3;
        const size_t tbase = (size_t)t * 4194304;
        const int mrow0 = mt*128 + wm*64;
        const int ncol0 = (nt & 7)*128 + wn*32;
        #pragma unroll
        for (int mi = 0; mi < 4; mi++)
            #pragma unroll
            for (int ni = 0; ni < 4; ni++) {
                int m0 = mrow0 + mi*16 + lrow;
                int m1 = m0 + 8;
                int n0 = ncol0 + ni*8 + lcol;
                int h = n0 >> 6, dk = n0 & 63;
                int b0 = m0 >> 10, s0 = m0 & 1023;
                int b1 = m1 >> 10, s1 = m1 & 1023;
                size_t i0 = tbase + ((size_t)((b0*HH + h)*SS + s0))*DKK + dk;
                size_t i1 = tbase + ((size_t)((b1*HH + h)*SS + s1))*DKK + dk;
                uint32_t hi, lo;
                split2(acc[mi][ni][0], acc[mi][ni][1], hi, lo);
                *(uint32_t*)&Chi[i0] = hi;
                *(uint32_t*)&Clo[i0] = lo;
                split2(acc[mi][ni][2], acc[mi][ni][3], hi, lo);
                *(uint32_t*)&Chi[i1] = hi;
                *(uint32_t*)&Clo[i1] = lo;
            }
    }
}

// ------------------------------------------------------------------
// Fused flash attention (round-5 shape: 128-row KV tiles, occ 1)
// + hoisted Q fragments + fully preloaded bias table.
// ------------------------------------------------------------------
#define T16 16384
#define FS_QH 0
#define FS_QL T16
#define FS_ST0 (2*T16)
#define FS_ST1 (6*T16)
#define FS_BIAS (10*T16)
#define FLASH_SMEM (10*T16 + 8192)

#define SWZ(r, c) ((uint32_t)((r)*128 + (((c) ^ ((r)&7))*16)))

__global__ void __launch_bounds__(256, 1) flash_kernel() {
    extern __shared__ __align__(128) char smem[];
    const uint32_t sb = smem_u32(smem);
    float* bias_all = (float*)(smem + FS_BIAS);   // [8][256]

    const int tid  = threadIdx.x;
    const int w = tid >> 5, lane = tid & 31;
    const int mbase = blockIdx.x * 128;
    const int bh = blockIdx.y;
    const int b = bh >> 4, h = bh & 15;

    const size_t base = (size_t)bh*SS*DKK;
    const __nv_bfloat16* Qh = g_qkv_hi + base + (size_t)mbase*DKK;
    const __nv_bfloat16* Ql = g_qkv_lo + base + (size_t)mbase*DKK;
    const __nv_bfloat16* Kh = g_qkv_hi + 4194304 + base;
    const __nv_bfloat16* Kl = g_qkv_lo + 4194304 + base;
    const __nv_bfloat16* Vh = g_qkv_hi + 8388608 + base;
    const __nv_bfloat16* Vl = g_qkv_lo + 8388608 + base;

    // prologue: Q (group with KV0)
    #pragma unroll
    for (int i = 0; i < 4; i++) {
        int id = tid + i*256;
        int r = id >> 3, c = id & 7;
        uint32_t off = SWZ(r, c);
        const size_t go = (size_t)r*64 + c*8;
        CP_ASYNC16(sb + FS_QH + off, Qh + go);
        CP_ASYNC16(sb + FS_QL + off, Ql + go);
    }
    #define ISSUE_KV(j, stoff) do { \
        const size_t _jo = (size_t)(j)*128*64; \
        _Pragma("unroll") \
        for (int _i = 0; _i < 4; _i++) { \
            int _id = tid + _i*256; \
            int _r = _id >> 3, _c = _id & 7; \
            uint32_t _off = SWZ(_r, _c); \
            const size_t _go = _jo + (size_t)_r*64 + _c*8; \
            CP_ASYNC16(sb + (stoff) + 0*T16 + _off, Kh + _go); \
            CP_ASYNC16(sb + (stoff) + 1*T16 + _off, Kl + _go); \
            CP_ASYNC16(sb + (stoff) + 2*T16 + _off, Vh + _go); \
            CP_ASYNC16(sb + (stoff) + 3*T16 + _off, Vl + _go); \
        } \
    } while (0)
    ISSUE_KV(0, FS_ST0); CP_COMMIT();
    ISSUE_KV(1, FS_ST1); CP_COMMIT();

    // preload ALL bias windows while cp.async is in flight
    for (int t = tid; t < 8*255; t += 256) {
        int jj = t / 255;
        int tt = t - jj*255;
        bias_all[jj*256 + tt] =
            g_bias[(size_t)(jj*128 - mbase + tt - 127 + (SS-1))*HH + h];
    }

    float Oacc[8][4];
    #pragma unroll
    for (int d = 0; d < 8; d++)
        #pragma unroll
        for (int q = 0; q < 4; q++) Oacc[d][q] = 0.f;
    float mrun0 = -1e30f, mrun1 = -1e30f, lrun0 = 0.f, lrun1 = 0.f;

    const int r0 = lane >> 2;
    const int colb = (lane & 3)*2;
    const int rl0 = w*16 + r0;
    const int rl1 = rl0 + 8;

    const int a_r = w*16 + (lane & 15);
    const int a_s = lane >> 4;
    const int b_r = ((lane >> 4) << 3) | (lane & 7);
    const int b_s = (lane >> 3) & 1;
    const int v_k = ((lane >> 3) & 1)*8 + (lane & 7);
    const int v_c = lane >> 4;

    // wait for Q+KV0, then hoist Q fragments into registers once
    CP_WAIT1();
    __syncthreads();
    uint32_t aqh[4][4], aql[4][4];
    #pragma unroll
    for (int ks = 0; ks < 4; ks++) {
        uint32_t aoff = SWZ(a_r, 2*ks + a_s);
        ldsm4(sb + FS_QH + aoff, aqh[ks][0], aqh[ks][1], aqh[ks][2], aqh[ks][3]);
        ldsm4(sb + FS_QL + aoff, aql[ks][0], aql[ks][1], aql[ks][2], aql[ks][3]);
    }

    for (int j = 0; j < 8; j++) {
        if (j > 0) {
            if (j < 7) { CP_WAIT1(); } else { CP_WAIT0(); }
            __syncthreads();
        }

        const uint32_t st = sb + ((j & 1) ? FS_ST1 : FS_ST0);
        const float* bias_s = bias_all + j*256;

        // ---- S = Q K^T (bf16x3) ----
        float sacc[16][4];
        #pragma unroll
        for (int nt = 0; nt < 16; nt++)
            #pragma unroll
            for (int q = 0; q < 4; q++) sacc[nt][q] = 0.f;

        #pragma unroll
        for (int ks = 0; ks < 4; ks++) {
            #pragma unroll
            for (int np = 0; np < 8; np++) {
                uint32_t kh[4], kl[4];
                uint32_t boff = SWZ(np*16 + b_r, 2*ks + b_s);
                ldsm4(st + 0*T16 + boff, kh[0], kh[1], kh[2], kh[3]);
                ldsm4(st + 1*T16 + boff, kl[0], kl[1], kl[2], kl[3]);
                mma16816(sacc[2*np],   aqh[ks], kh[0], kh[1]);
                mma16816(sacc[2*np],   aqh[ks], kl[0], kl[1]);
                mma16816(sacc[2*np],   aql[ks], kh[0], kh[1]);
                mma16816(sacc[2*np+1], aqh[ks], kh[2], kh[3]);
                mma16816(sacc[2*np+1], aqh[ks], kl[2], kl[3]);
                mma16816(sacc[2*np+1], aql[ks], kh[2], kh[3]);
            }
        }

        // ---- bias ----
        #pragma unroll
        for (int nt = 0; nt < 16; nt++) {
            int col = nt*8 + colb;
            sacc[nt][0] += bias_s[col     - rl0 + 127];
            sacc[nt][1] += bias_s[col + 1 - rl0 + 127];
            sacc[nt][2] += bias_s[col     - rl1 + 127];
            sacc[nt][3] += bias_s[col + 1 - rl1 + 127];
        }

        // ---- online softmax ----
        float mx0 = -1e30f, mx1 = -1e30f;
        #pragma unroll
        for (int nt = 0; nt < 16; nt++) {
            mx0 = fmaxf(mx0, fmaxf(sacc[nt][0], sacc[nt][1]));
            mx1 = fmaxf(mx1, fmaxf(sacc[nt][2], sacc[nt][3]));
        }
        mx0 = fmaxf(mx0, __shfl_xor_sync(0xffffffffu, mx0, 1));
        mx0 = fmaxf(mx0, __shfl_xor_sync(0xffffffffu, mx0, 2));
        mx1 = fmaxf(mx1, __shfl_xor_sync(0xffffffffu, mx1, 1));
        mx1 = fmaxf(mx1, __shfl_xor_sync(0xffffffffu, mx1, 2));

        float mn0 = fmaxf(mrun0, mx0);
        float mn1 = fmaxf(mrun1, mx1);
        float al0 = __expf(mrun0 - mn0);
        float al1 = __expf(mrun1 - mn1);
        mrun0 = mn0; mrun1 = mn1;

        float rs0 = 0.f, rs1 = 0.f;
        #pragma unroll
        for (int nt = 0; nt < 16; nt++) {
            sacc[nt][0] = __expf(sacc[nt][0] - mn0);
            sacc[nt][1] = __expf(sacc[nt][1] - mn0);
            sacc[nt][2] = __expf(sacc[nt][2] - mn1);
            sacc[nt][3] = __expf(sacc[nt][3] - mn1);
            rs0 += sacc[nt][0] + sacc[nt][1];
            rs1 += sacc[nt][2] + sacc[nt][3];
        }
        rs0 += __shfl_xor_sync(0xffffffffu, rs0, 1);
        rs0 += __shfl_xor_sync(0xffffffffu, rs0, 2);
        rs1 += __shfl_xor_sync(0xffffffffu, rs1, 1);
        rs1 += __shfl_xor_sync(0xffffffffu, rs1, 2);
        lrun0 = lrun0*al0 + rs0;
        lrun1 = lrun1*al1 + rs1;

        #pragma unroll
        for (int d = 0; d < 8; d++) {
            Oacc[d][0] *= al0; Oacc[d][1] *= al0;
            Oacc[d][2] *= al1; Oacc[d][3] *= al1;
        }

        // ---- O += P V (bf16x3) ----
        #pragma unroll
        for (int ks = 0; ks < 8; ks++) {
            uint32_t ph[4], pl[4];
            split2(sacc[2*ks][0],   sacc[2*ks][1],   ph[0], pl[0]);
            split2(sacc[2*ks][2],   sacc[2*ks][3],   ph[1], pl[1]);
            split2(sacc[2*ks+1][0], sacc[2*ks+1][1], ph[2], pl[2]);
            split2(sacc[2*ks+1][2], sacc[2*ks+1][3], ph[3], pl[3]);
            #pragma unroll
            for (int dp = 0; dp < 4; dp++) {
                uint32_t vh[4], vl[4];
                uint32_t voff = SWZ(ks*16 + v_k, dp*2 + v_c);
                ldsm4t(st + 2*T16 + voff, vh[0], vh[1], vh[2], vh[3]);
                ldsm4t(st + 3*T16 + voff, vl[0], vl[1], vl[2], vl[3]);
                mma16816(Oacc[2*dp],   ph, vh[0], vh[1]);
                mma16816(Oacc[2*dp],   ph, vl[0], vl[1]);
                mma16816(Oacc[2*dp],   pl, vh[0], vh[1]);
                mma16816(Oacc[2*dp+1], ph, vh[2], vh[3]);
                mma16816(Oacc[2*dp+1], ph, vl[2], vl[3]);
                mma16816(Oacc[2*dp+1], pl, vh[2], vh[3]);
            }
        }

        __syncthreads();   // all warps done reading stage j&1
        if (j + 2 < 8) {
            ISSUE_KV(j + 2, ((j & 1) ? FS_ST1 : FS_ST0));
            CP_COMMIT();
        }
    }
    #undef ISSUE_KV

    // ---- epilogue: normalize + write ctx as bf16 hi/lo ----
    float inv0 = 1.0f / lrun0;
    float inv1 = 1.0f / lrun1;
    int m0 = mbase + rl0;
    int m1 = mbase + rl1;
    #pragma unroll
    for (int dt = 0; dt < 8; dt++) {
        int d = dt*8 + colb;
        size_t i0 = ((size_t)(b*SS + m0))*DD + h*DKK + d;
        size_t i1 = ((size_t)(b*SS + m1))*DD + h*DKK + d;
        uint32_t hi, lo;
        split2(Oacc[dt][0]*inv0, Oacc[dt][1]*inv0, hi, lo);
        *(uint32_t*)&g_ctx_hi[i0] = hi;
        *(uint32_t*)&g_ctx_lo[i0] = lo;
        split2(Oacc[dt][2]*inv1, Oacc[dt][3]*inv1, hi, lo);
        *(uint32_t*)&g_ctx_hi[i1] = hi;
        *(uint32_t*)&g_ctx_lo[i1] = lo;
    }
}

// ------------------------------------------------------------------
extern "C" void kernel_launch(void* const* d_in, const int* in_sizes, int n_in,
                              void* d_out, int out_size) {
    const float* hidden   = (const float*)d_in[0];
    const float* Wq       = (const float*)d_in[1];
    const float* Wk       = (const float*)d_in[2];
    const float* Wv       = (const float*)d_in[3];
    const float* Wo       = (const float*)d_in[4];
    const float* rel_bias = (const float*)d_in[5];
    float* out = (float*)d_out;

    __nv_bfloat16 *pahi, *palo, *pwhi, *pwlo, *pqkvh, *pqkvl, *pchi, *pclo;
    cudaGetSymbolAddress((void**)&pahi, g_ahi);
    cudaGetSymbolAddress((void**)&palo, g_alo);
    cudaGetSymbolAddress((void**)&pwhi, g_whi);
    cudaGetSymbolAddress((void**)&pwlo, g_wlo);
    cudaGetSymbolAddress((void**)&pqkvh, g_qkv_hi);
    cudaGetSymbolAddress((void**)&pqkvl, g_qkv_lo);
    cudaGetSymbolAddress((void**)&pchi, g_ctx_hi);
    cudaGetSymbolAddress((void**)&pclo, g_ctx_lo);

    cudaFuncSetAttribute(gemm_mma_kernel,
                         cudaFuncAttributeMaxDynamicSharedMemorySize, GEMM_SMEM);
    cudaFuncSetAttribute(flash_kernel,
                         cudaFuncAttributeMaxDynamicSharedMemorySize, FLASH_SMEM);

    const int nA = 4096*1024;

    bias_kernel<<<((2*SS-1)*HH + 255)/256, 256>>>(rel_bias);
    split_kernel<<<(nA + 255)/256, 256>>>(hidden, pahi, palo, nA);
    split4_kernel<<<(4194304 + 255)/256, 256>>>(Wq, Wk, Wv, Wo, pwhi, pwlo);

    // fused QKV projection -> bf16 hi/lo head-split
    gemm_mma_kernel<<<dim3(24, 32), 256, GEMM_SMEM>>>(
        pahi, palo, pwhi, pwlo, nullptr, pqkvh, pqkvl, 2);

    // fused attention
    flash_kernel<<<dim3(8, BH), 256, FLASH_SMEM>>>();

    // output projection (fp32 out)
    gemm_mma_kernel<<<dim3(8, 32), 256, GEMM_SMEM>>>(
        pchi, pclo, pwhi + 3145728, pwlo + 3145728, out, nullptr, nullptr, 0);
}

// round 9
// speedup vs baseline: 1.6376x; 1.0684x over previous
#include <cuda_runtime.h>
#include <cuda_bf16.h>
#include <cuda_fp16.h>
#include <math.h>
#include <stdint.h>

#define BB 4
#define SS 1024
#define DD 1024
#define HH 16
#define DKK 64
#define BH (BB*HH)

// ---- scratch (device globals; no allocation allowed) ----
__device__ float g_bias[(2*SS-1)*HH];

__device__ __align__(16) __nv_bfloat16 g_ahi[4096*1024];     // hidden hi
__device__ __align__(16) __nv_bfloat16 g_alo[4096*1024];     // hidden lo
__device__ __align__(16) __nv_bfloat16 g_whi[4096*1024];     // Wq|Wk|Wv|Wo hi
__device__ __align__(16) __nv_bfloat16 g_wlo[4096*1024];
// q|k bf16 hi/lo; v slot holds fp16 hi/lo (same 16-bit storage)
__device__ __align__(16) __nv_bfloat16 g_qkv_hi[3*4194304];
__device__ __align__(16) __nv_bfloat16 g_qkv_lo[3*4194304];
__device__ __align__(16) __nv_bfloat16 g_ctx_hi[4096*1024];  // ctx [b*s][h*dk]
__device__ __align__(16) __nv_bfloat16 g_ctx_lo[4096*1024];

// ================= PTX helpers (baseline ISA only) =================
__device__ __forceinline__ uint32_t smem_u32(const void* p) {
    uint32_t a;
    asm("{ .reg .u64 t; cvta.to.shared.u64 t, %1; cvt.u32.u64 %0, t; }"
        : "=r"(a) : "l"(p));
    return a;
}

#define CP_ASYNC16(sa, ga) \
    asm volatile("cp.async.cg.shared.global [%0], [%1], 16;" \
        :: "r"(sa), "l"(ga) : "memory")
#define CP_COMMIT() asm volatile("cp.async.commit_group;" ::: "memory")
#define CP_WAIT1()  asm volatile("cp.async.wait_group 1;" ::: "memory")
#define CP_WAIT0()  asm volatile("cp.async.wait_group 0;" ::: "memory")

__device__ __forceinline__ void ldsm4(uint32_t addr, uint32_t& r0, uint32_t& r1,
                                      uint32_t& r2, uint32_t& r3) {
    asm volatile("ldmatrix.sync.aligned.m8n8.x4.shared.b16 {%0,%1,%2,%3}, [%4];"
        : "=r"(r0), "=r"(r1), "=r"(r2), "=r"(r3) : "r"(addr));
}
__device__ __forceinline__ void ldsm4t(uint32_t addr, uint32_t& r0, uint32_t& r1,
                                       uint32_t& r2, uint32_t& r3) {
    asm volatile("ldmatrix.sync.aligned.m8n8.x4.trans.shared.b16 {%0,%1,%2,%3}, [%4];"
        : "=r"(r0), "=r"(r1), "=r"(r2), "=r"(r3) : "r"(addr));
}

__device__ __forceinline__ void mma16816(float* d, const uint32_t* a,
                                         uint32_t b0, uint32_t b1) {
    asm volatile("mma.sync.aligned.m16n8k16.row.col.f32.bf16.bf16.f32 "
        "{%0,%1,%2,%3}, {%4,%5,%6,%7}, {%8,%9}, {%0,%1,%2,%3};"
        : "+f"(d[0]), "+f"(d[1]), "+f"(d[2]), "+f"(d[3])
        : "r"(a[0]), "r"(a[1]), "r"(a[2]), "r"(a[3]), "r"(b0), "r"(b1));
}
__device__ __forceinline__ void mma16816h(float* d, const uint32_t* a,
                                          uint32_t b0, uint32_t b1) {
    asm volatile("mma.sync.aligned.m16n8k16.row.col.f32.f16.f16.f32 "
        "{%0,%1,%2,%3}, {%4,%5,%6,%7}, {%8,%9}, {%0,%1,%2,%3};"
        : "+f"(d[0]), "+f"(d[1]), "+f"(d[2]), "+f"(d[3])
        : "r"(a[0]), "r"(a[1]), "r"(a[2]), "r"(a[3]), "r"(b0), "r"(b1));
}

__device__ __forceinline__ void split2(float x0, float x1, uint32_t& hi, uint32_t& lo) {
    __nv_bfloat16 h0 = __float2bfloat16(x0);
    __nv_bfloat16 h1 = __float2bfloat16(x1);
    __nv_bfloat162 th; th.x = h0; th.y = h1;
    hi = *(uint32_t*)&th;
    __nv_bfloat162 tl;
    tl.x = __float2bfloat16(x0 - __bfloat162float(h0));
    tl.y = __float2bfloat16(x1 - __bfloat162float(h1));
    lo = *(uint32_t*)&tl;
}
__device__ __forceinline__ void split2h(float x0, float x1, uint32_t& hi, uint32_t& lo) {
    __half h0 = __float2half_rn(x0);
    __half h1 = __float2half_rn(x1);
    __half2 th = __halves2half2(h0, h1);
    hi = *(uint32_t*)&th;
    __half2 tl = __halves2half2(__float2half_rn(x0 - __half2float(h0)),
                                __float2half_rn(x1 - __half2float(h1)));
    lo = *(uint32_t*)&tl;
}

// ------------------------------------------------------------------
// One kernel: split hidden (4M) + all four weights (4M)
// ------------------------------------------------------------------
__global__ void split_all_kernel(const float* __restrict__ hid,
                                 const float* __restrict__ w0, const float* __restrict__ w1,
                                 const float* __restrict__ w2, const float* __restrict__ w3,
                                 __nv_bfloat16* __restrict__ ahi, __nv_bfloat16* __restrict__ alo,
                                 __nv_bfloat16* __restrict__ whi, __nv_bfloat16* __restrict__ wlo) {
    int i = blockIdx.x * blockDim.x + threadIdx.x;   // 0..8M-1
    float v;
    __nv_bfloat16* hi;
    __nv_bfloat16* lo;
    int dst;
    if (i < 4194304) {
        v = hid[i];
        hi = ahi; lo = alo; dst = i;
    } else {
        int j = i - 4194304;
        int t = j >> 20;
        int off = j & 1048575;
        const float* src = (t == 0) ? w0 : (t == 1) ? w1 : (t == 2) ? w2 : w3;
        v = src[off];
        hi = whi; lo = wlo; dst = j;
    }
    __nv_bfloat16 h = __float2bfloat16(v);
    hi[dst] = h;
    lo[dst] = __float2bfloat16(v - __bfloat162float(h));
}

// ------------------------------------------------------------------
__global__ void bias_kernel(const float* __restrict__ rel_bias) {
    int idx = blockIdx.x * blockDim.x + threadIdx.x;
    const int total = (2*SS-1)*HH;
    if (idx >= total) return;
    int d = idx / HH;
    int h = idx - d*HH;
    int rp = d - (SS - 1);
    int rb = (rp > 0) ? 16 : 0;
    int n = rp < 0 ? -rp : rp;
    int b;
    if (n < 8) {
        b = n;
    } else {
        double v = log((double)n / 8.0) / log(16.0) * 8.0;
        int large = 8 + (int)v;
        b = large < 15 ? large : 15;
    }
    g_bias[idx] = rel_bias[(rb + b)*HH + h];
}

// ------------------------------------------------------------------
// HMMA bf16x3 GEMM. mode 0: fp32 row-major out.
// mode 2: QKV fused; Q,K -> bf16 hi/lo; V (t==2) -> fp16 hi/lo.
// ------------------------------------------------------------------
#define BKG 32
#define STAGES 3
#define TENSOR_BYTES (128*64)
#define STAGE_BYTES  (4*TENSOR_BYTES)
#define GEMM_SMEM    (STAGES*STAGE_BYTES)

__global__ void __launch_bounds__(256, 2) gemm_mma_kernel(
    const __nv_bfloat16* __restrict__ Ahi, const __nv_bfloat16* __restrict__ Alo,
    const __nv_bfloat16* __restrict__ Whi, const __nv_bfloat16* __restrict__ Wlo,
    float* __restrict__ C,
    __nv_bfloat16* __restrict__ Chi, __nv_bfloat16* __restrict__ Clo,
    int mode)
{
    extern __shared__ __align__(128) char smem[];
    const uint32_t sb = smem_u32(smem);
    const int tid  = threadIdx.x;
    const int warp = tid >> 5, lane = tid & 31;
    const int wm = warp >> 2, wn = warp & 3;
    const int nt = blockIdx.x, mt = blockIdx.y;

    const __nv_bfloat16* src0 = Ahi + (size_t)(mt*128)*1024;
    const __nv_bfloat16* src1 = Alo + (size_t)(mt*128)*1024;
    const __nv_bfloat16* src2 = Whi + (size_t)(nt*128)*1024;
    const __nv_bfloat16* src3 = Wlo + (size_t)(nt*128)*1024;
    const __nv_bfloat16* mysrc = (tid < 64) ? src0 : (tid < 128) ? src1
                               : (tid < 192) ? src2 : src3;
    const int t4 = tid >> 6;
    const int li = tid & 63;

    #define ISSUE(it) do { \
        int _stg = (it) % STAGES; \
        uint32_t _sbase = sb + _stg*STAGE_BYTES + t4*TENSOR_BYTES; \
        const __nv_bfloat16* _g = mysrc + (it)*BKG; \
        _Pragma("unroll") \
        for (int _j = 0; _j < 8; _j++) { \
            int _ch = li + _j*64; \
            int _r = _ch >> 2, _c = _ch & 3; \
            int _cs = _c ^ ((_r >> 1) & 3); \
            CP_ASYNC16(_sbase + _r*64 + _cs*16, _g + (size_t)_r*1024 + _c*8); \
        } \
    } while (0)

    ISSUE(0); CP_COMMIT();
    ISSUE(1); CP_COMMIT();

    float acc[4][4][4];
    #pragma unroll
    for (int i = 0; i < 4; i++)
        #pragma unroll
        for (int j = 0; j < 4; j++)
            #pragma unroll
            for (int q = 0; q < 4; q++) acc[i][j][q] = 0.f;

    const int arow = lane & 15;
    const int asel = lane >> 4;
    const int brow = ((lane >> 4) << 3) | (lane & 7);
    const int bsel = (lane >> 3) & 1;

    for (int it = 0; it < 32; it++) {
        CP_WAIT1();
        __syncthreads();
        if (it + 2 < 32) ISSUE(it + 2);
        CP_COMMIT();

        const uint32_t st = sb + (it % STAGES)*STAGE_BYTES;
        #pragma unroll
        for (int ks = 0; ks < 2; ks++) {
            uint32_t ah[4][4], al[4][4];
            #pragma unroll
            for (int mi = 0; mi < 4; mi++) {
                int r = wm*64 + mi*16 + arow;
                int c = 2*ks + asel;
                uint32_t off = (uint32_t)(r*64 + ((c ^ ((r>>1)&3))*16));
                ldsm4(st + off,               ah[mi][0], ah[mi][1], ah[mi][2], ah[mi][3]);
                ldsm4(st + TENSOR_BYTES + off, al[mi][0], al[mi][1], al[mi][2], al[mi][3]);
            }
            uint32_t bh2[2][4], bl2[2][4];
            #pragma unroll
            for (int np = 0; np < 2; np++) {
                int r = wn*32 + np*16 + brow;
                int c = 2*ks + bsel;
                uint32_t off = (uint32_t)(r*64 + ((c ^ ((r>>1)&3))*16));
                ldsm4(st + 2*TENSOR_BYTES + off, bh2[np][0], bh2[np][1], bh2[np][2], bh2[np][3]);
                ldsm4(st + 3*TENSOR_BYTES + off, bl2[np][0], bl2[np][1], bl2[np][2], bl2[np][3]);
            }
            #pragma unroll
            for (int mi = 0; mi < 4; mi++)
                #pragma unroll
                for (int ni = 0; ni < 4; ni++) {
                    uint32_t b0h = bh2[ni>>1][(ni&1)*2], b1h = bh2[ni>>1][(ni&1)*2+1];
                    uint32_t b0l = bl2[ni>>1][(ni&1)*2], b1l = bl2[ni>>1][(ni&1)*2+1];
                    mma16816(acc[mi][ni], ah[mi], b0h, b1h);
                    mma16816(acc[mi][ni], ah[mi], b0l, b1l);
                    mma16816(acc[mi][ni], al[mi], b0h, b1h);
                }
        }
    }
    #undef ISSUE

    const int lrow = lane >> 2;
    const int lcol = (lane & 3)*2;
    if (mode == 0) {
        const int mrow0 = mt*128 + wm*64;
        const int ncol0 = nt*128 + wn*32;
        #pragma unroll
        for (int mi = 0; mi < 4; mi++)
            #pragma unroll
            for (int ni = 0; ni < 4; ni++) {
                int m0 = mrow0 + mi*16 + lrow;
                int n0 = ncol0 + ni*8 + lcol;
                *(float2*)(C + (size_t)m0*1024 + n0) =
                    make_float2(acc[mi][ni][0], acc[mi][ni][1]);
                *(float2*)(C + (size_t)(m0+8)*1024 + n0) =
                    make_float2(acc[mi][ni][2], acc[mi][ni][3]);
            }
    } else {
        const int t = nt >> 3;
        const size_t tbase = (size_t)t * 4194304;
        const int mrow0 = mt*128 + wm*64;
        const int ncol0 = (nt & 7)*128 + wn*32;
        #pragma unroll
        for (int mi = 0; mi < 4; mi++)
            #pragma unroll
            for (int ni = 0; ni < 4; ni++) {
                int m0 = mrow0 + mi*16 + lrow;
                int m1 = m0 + 8;
                int n0 = ncol0 + ni*8 + lcol;
                int h = n0 >> 6, dk = n0 & 63;
                int b0 = m0 >> 10, s0 = m0 & 1023;
                int b1 = m1 >> 10, s1 = m1 & 1023;
                size_t i0 = tbase + ((size_t)((b0*HH + h)*SS + s0))*DKK + dk;
                size_t i1 = tbase + ((size_t)((b1*HH + h)*SS + s1))*DKK + dk;
                uint32_t hi, lo;
                if (t == 2) {
                    split2h(acc[mi][ni][0], acc[mi][ni][1], hi, lo);
                    *(uint32_t*)&Chi[i0] = hi;
                    *(uint32_t*)&Clo[i0] = lo;
                    split2h(acc[mi][ni][2], acc[mi][ni][3], hi, lo);
                    *(uint32_t*)&Chi[i1] = hi;
                    *(uint32_t*)&Clo[i1] = lo;
                } else {
                    split2(acc[mi][ni][0], acc[mi][ni][1], hi, lo);
                    *(uint32_t*)&Chi[i0] = hi;
                    *(uint32_t*)&Clo[i0] = lo;
                    split2(acc[mi][ni][2], acc[mi][ni][3], hi, lo);
                    *(uint32_t*)&Chi[i1] = hi;
                    *(uint32_t*)&Clo[i1] = lo;
                }
            }
    }
}

// ------------------------------------------------------------------
// Fused flash attention. QK^T bf16x3; PV fp16 (P single, V hi/lo) = 2 MMAs.
// ------------------------------------------------------------------
#define T16 16384
#define FS_QH 0
#define FS_QL T16
#define FS_ST0 (2*T16)
#define FS_ST1 (6*T16)
#define FS_BIAS (10*T16)
#define FLASH_SMEM (10*T16 + 8192)

#define SWZ(r, c) ((uint32_t)((r)*128 + (((c) ^ ((r)&7))*16)))

__global__ void __launch_bounds__(256, 1) flash_kernel() {
    extern __shared__ __align__(128) char smem[];
    const uint32_t sb = smem_u32(smem);
    float* bias_all = (float*)(smem + FS_BIAS);   // [8][256]

    const int tid  = threadIdx.x;
    const int w = tid >> 5, lane = tid & 31;
    const int mbase = blockIdx.x * 128;
    const int bh = blockIdx.y;
    const int b = bh >> 4, h = bh & 15;

    const size_t base = (size_t)bh*SS*DKK;
    const __nv_bfloat16* Qh = g_qkv_hi + base + (size_t)mbase*DKK;
    const __nv_bfloat16* Ql = g_qkv_lo + base + (size_t)mbase*DKK;
    const __nv_bfloat16* Kh = g_qkv_hi + 4194304 + base;
    const __nv_bfloat16* Kl = g_qkv_lo + 4194304 + base;
    const __nv_bfloat16* Vh = g_qkv_hi + 8388608 + base;   // fp16 bits
    const __nv_bfloat16* Vl = g_qkv_lo + 8388608 + base;   // fp16 bits

    #pragma unroll
    for (int i = 0; i < 4; i++) {
        int id = tid + i*256;
        int r = id >> 3, c = id & 7;
        uint32_t off = SWZ(r, c);
        const size_t go = (size_t)r*64 + c*8;
        CP_ASYNC16(sb + FS_QH + off, Qh + go);
        CP_ASYNC16(sb + FS_QL + off, Ql + go);
    }
    #define ISSUE_KV(j, stoff) do { \
        const size_t _jo = (size_t)(j)*128*64; \
        _Pragma("unroll") \
        for (int _i = 0; _i < 4; _i++) { \
            int _id = tid + _i*256; \
            int _r = _id >> 3, _c = _id & 7; \
            uint32_t _off = SWZ(_r, _c); \
            const size_t _go = _jo + (size_t)_r*64 + _c*8; \
            CP_ASYNC16(sb + (stoff) + 0*T16 + _off, Kh + _go); \
            CP_ASYNC16(sb + (stoff) + 1*T16 + _off, Kl + _go); \
            CP_ASYNC16(sb + (stoff) + 2*T16 + _off, Vh + _go); \
            CP_ASYNC16(sb + (stoff) + 3*T16 + _off, Vl + _go); \
        } \
    } while (0)
    ISSUE_KV(0, FS_ST0); CP_COMMIT();
    ISSUE_KV(1, FS_ST1); CP_COMMIT();

    // preload ALL bias windows while cp.async is in flight
    for (int t = tid; t < 8*255; t += 256) {
        int jj = t / 255;
        int tt = t - jj*255;
        bias_all[jj*256 + tt] =
            g_bias[(size_t)(jj*128 - mbase + tt - 127 + (SS-1))*HH + h];
    }

    float Oacc[8][4];
    #pragma unroll
    for (int d = 0; d < 8; d++)
        #pragma unroll
        for (int q = 0; q < 4; q++) Oacc[d][q] = 0.f;
    float mrun0 = -1e30f, mrun1 = -1e30f, lrun0 = 0.f, lrun1 = 0.f;

    const int r0 = lane >> 2;
    const int colb = (lane & 3)*2;
    const int rl0 = w*16 + r0;
    const int rl1 = rl0 + 8;

    const int a_r = w*16 + (lane & 15);
    const int a_s = lane >> 4;
    const int b_r = ((lane >> 4) << 3) | (lane & 7);
    const int b_s = (lane >> 3) & 1;
    const int v_k = ((lane >> 3) & 1)*8 + (lane & 7);
    const int v_c = lane >> 4;

    CP_WAIT1();
    __syncthreads();
    uint32_t aqh[4][4], aql[4][4];
    #pragma unroll
    for (int ks = 0; ks < 4; ks++) {
        uint32_t aoff = SWZ(a_r, 2*ks + a_s);
        ldsm4(sb + FS_QH + aoff, aqh[ks][0], aqh[ks][1], aqh[ks][2], aqh[ks][3]);
        ldsm4(sb + FS_QL + aoff, aql[ks][0], aql[ks][1], aql[ks][2], aql[ks][3]);
    }

    for (int j = 0; j < 8; j++) {
        if (j > 0) {
            if (j < 7) { CP_WAIT1(); } else { CP_WAIT0(); }
            __syncthreads();
        }

        const uint32_t st = sb + ((j & 1) ? FS_ST1 : FS_ST0);
        const float* bias_s = bias_all + j*256;

        // ---- S = Q K^T (bf16x3) ----
        float sacc[16][4];
        #pragma unroll
        for (int nt = 0; nt < 16; nt++)
            #pragma unroll
            for (int q = 0; q < 4; q++) sacc[nt][q] = 0.f;

        #pragma unroll
        for (int ks = 0; ks < 4; ks++) {
            #pragma unroll
            for (int np = 0; np < 8; np++) {
                uint32_t kh[4], kl[4];
                uint32_t boff = SWZ(np*16 + b_r, 2*ks + b_s);
                ldsm4(st + 0*T16 + boff, kh[0], kh[1], kh[2], kh[3]);
                ldsm4(st + 1*T16 + boff, kl[0], kl[1], kl[2], kl[3]);
                mma16816(sacc[2*np],   aqh[ks], kh[0], kh[1]);
                mma16816(sacc[2*np],   aqh[ks], kl[0], kl[1]);
                mma16816(sacc[2*np],   aql[ks], kh[0], kh[1]);
                mma16816(sacc[2*np+1], aqh[ks], kh[2], kh[3]);
                mma16816(sacc[2*np+1], aqh[ks], kl[2], kl[3]);
                mma16816(sacc[2*np+1], aql[ks], kh[2], kh[3]);
            }
        }

        // ---- bias ----
        #pragma unroll
        for (int nt = 0; nt < 16; nt++) {
            int col = nt*8 + colb;
            sacc[nt][0] += bias_s[col     - rl0 + 127];
            sacc[nt][1] += bias_s[col + 1 - rl0 + 127];
            sacc[nt][2] += bias_s[col     - rl1 + 127];
            sacc[nt][3] += bias_s[col + 1 - rl1 + 127];
        }

        // ---- online softmax ----
        float mx0 = -1e30f, mx1 = -1e30f;
        #pragma unroll
        for (int nt = 0; nt < 16; nt++) {
            mx0 = fmaxf(mx0, fmaxf(sacc[nt][0], sacc[nt][1]));
            mx1 = fmaxf(mx1, fmaxf(sacc[nt][2], sacc[nt][3]));
        }
        mx0 = fmaxf(mx0, __shfl_xor_sync(0xffffffffu, mx0, 1));
        mx0 = fmaxf(mx0, __shfl_xor_sync(0xffffffffu, mx0, 2));
        mx1 = fmaxf(mx1, __shfl_xor_sync(0xffffffffu, mx1, 1));
        mx1 = fmaxf(mx1, __shfl_xor_sync(0xffffffffu, mx1, 2));

        float mn0 = fmaxf(mrun0, mx0);
        float mn1 = fmaxf(mrun1, mx1);
        float al0 = __expf(mrun0 - mn0);
        float al1 = __expf(mrun1 - mn1);
        mrun0 = mn0; mrun1 = mn1;

        float rs0 = 0.f, rs1 = 0.f;
        #pragma unroll
        for (int nt = 0; nt < 16; nt++) {
            sacc[nt][0] = __expf(sacc[nt][0] - mn0);
            sacc[nt][1] = __expf(sacc[nt][1] - mn0);
            sacc[nt][2] = __expf(sacc[nt][2] - mn1);
            sacc[nt][3] = __expf(sacc[nt][3] - mn1);
            rs0 += sacc[nt][0] + sacc[nt][1];
            rs1 += sacc[nt][2] + sacc[nt][3];
        }
        rs0 += __shfl_xor_sync(0xffffffffu, rs0, 1);
        rs0 += __shfl_xor_sync(0xffffffffu, rs0, 2);
        rs1 += __shfl_xor_sync(0xffffffffu, rs1, 1);
        rs1 += __shfl_xor_sync(0xffffffffu, rs1, 2);
        lrun0 = lrun0*al0 + rs0;
        lrun1 = lrun1*al1 + rs1;

        #pragma unroll
        for (int d = 0; d < 8; d++) {
            Oacc[d][0] *= al0; Oacc[d][1] *= al0;
            Oacc[d][2] *= al1; Oacc[d][3] *= al1;
        }

        // ---- O += P V (fp16: P single, V hi+lo) ----
        #pragma unroll
        for (int ks = 0; ks < 8; ks++) {
            uint32_t ph[4];
            {
                __half2 t0 = __floats2half2_rn(sacc[2*ks][0],   sacc[2*ks][1]);
                __half2 t1 = __floats2half2_rn(sacc[2*ks][2],   sacc[2*ks][3]);
                __half2 t2 = __floats2half2_rn(sacc[2*ks+1][0], sacc[2*ks+1][1]);
                __half2 t3 = __floats2half2_rn(sacc[2*ks+1][2], sacc[2*ks+1][3]);
                ph[0] = *(uint32_t*)&t0;
                ph[1] = *(uint32_t*)&t1;
                ph[2] = *(uint32_t*)&t2;
                ph[3] = *(uint32_t*)&t3;
            }
            #pragma unroll
            for (int dp = 0; dp < 4; dp++) {
                uint32_t vh[4], vl[4];
                uint32_t voff = SWZ(ks*16 + v_k, dp*2 + v_c);
                ldsm4t(st + 2*T16 + voff, vh[0], vh[1], vh[2], vh[3]);
                ldsm4t(st + 3*T16 + voff, vl[0], vl[1], vl[2], vl[3]);
                mma16816h(Oacc[2*dp],   ph, vh[0], vh[1]);
                mma16816h(Oacc[2*dp],   ph, vl[0], vl[1]);
                mma16816h(Oacc[2*dp+1], ph, vh[2], vh[3]);
                mma16816h(Oacc[2*dp+1], ph, vl[2], vl[3]);
            }
        }

        __syncthreads();
        if (j + 2 < 8) {
            ISSUE_KV(j + 2, ((j & 1) ? FS_ST1 : FS_ST0));
            CP_COMMIT();
        }
    }
    #undef ISSUE_KV

    // ---- epilogue: normalize + write ctx as bf16 hi/lo ----
    float inv0 = 1.0f / lrun0;
    float inv1 = 1.0f / lrun1;
    int m0 = mbase + rl0;
    int m1 = mbase + rl1;
    #pragma unroll
    for (int dt = 0; dt < 8; dt++) {
        int d = dt*8 + colb;
        size_t i0 = ((size_t)(b*SS + m0))*DD + h*DKK + d;
        size_t i1 = ((size_t)(b*SS + m1))*DD + h*DKK + d;
        uint32_t hi, lo;
        split2(Oacc[dt][0]*inv0, Oacc[dt][1]*inv0, hi, lo);
        *(uint32_t*)&g_ctx_hi[i0] = hi;
        *(uint32_t*)&g_ctx_lo[i0] = lo;
        split2(Oacc[dt][2]*inv1, Oacc[dt][3]*inv1, hi, lo);
        *(uint32_t*)&g_ctx_hi[i1] = hi;
        *(uint32_t*)&g_ctx_lo[i1] = lo;
    }
}

// ------------------------------------------------------------------
extern "C" void kernel_launch(void* const* d_in, const int* in_sizes, int n_in,
                              void* d_out, int out_size) {
    const float* hidden   = (const float*)d_in[0];
    const float* Wq       = (const float*)d_in[1];
    const float* Wk       = (const float*)d_in[2];
    const float* Wv       = (const float*)d_in[3];
    const float* Wo       = (const float*)d_in[4];
    const float* rel_bias = (const float*)d_in[5];
    float* out = (float*)d_out;

    __nv_bfloat16 *pahi, *palo, *pwhi, *pwlo, *pqkvh, *pqkvl, *pchi, *pclo;
    cudaGetSymbolAddress((void**)&pahi, g_ahi);
    cudaGetSymbolAddress((void**)&palo, g_alo);
    cudaGetSymbolAddress((void**)&pwhi, g_whi);
    cudaGetSymbolAddress((void**)&pwlo, g_wlo);
    cudaGetSymbolAddress((void**)&pqkvh, g_qkv_hi);
    cudaGetSymbolAddress((void**)&pqkvl, g_qkv_lo);
    cudaGetSymbolAddress((void**)&pchi, g_ctx_hi);
    cudaGetSymbolAddress((void**)&pclo, g_ctx_lo);

    cudaFuncSetAttribute(gemm_mma_kernel,
                         cudaFuncAttributeMaxDynamicSharedMemorySize, GEMM_SMEM);
    cudaFuncSetAttribute(flash_kernel,
                         cudaFuncAttributeMaxDynamicSharedMemorySize, FLASH_SMEM);

    bias_kernel<<<((2*SS-1)*HH + 255)/256, 256>>>(rel_bias);
    split_all_kernel<<<(8388608 + 255)/256, 256>>>(
        hidden, Wq, Wk, Wv, Wo, pahi, palo, pwhi, pwlo);

    // fused QKV projection -> Q,K bf16 hi/lo; V fp16 hi/lo
    gemm_mma_kernel<<<dim3(24, 32), 256, GEMM_SMEM>>>(
        pahi, palo, pwhi, pwlo, nullptr, pqkvh, pqkvl, 2);

    // fused attention
    flash_kernel<<<dim3(8, BH), 256, FLASH_SMEM>>>();

    // output projection (fp32 out)
    gemm_mma_kernel<<<dim3(8, 32), 256, GEMM_SMEM>>>(
        pchi, pclo, pwhi + 3145728, pwlo + 3145728, out, nullptr, nullptr, 0);
}

// round 10
// speedup vs baseline: 1.7979x; 1.0979x over previous
#include <cuda_runtime.h>
#include <cuda_bf16.h>
#include <cuda_fp16.h>
#include <math.h>
#include <stdint.h>

#define BB 4
#define SS 1024
#define DD 1024
#define HH 16
#define DKK 64
#define BH (BB*HH)

// ---- scratch (device globals; no allocation allowed) ----
__device__ float g_bias[(2*SS-1)*HH];

__device__ __align__(16) __nv_bfloat16 g_ahi[4096*1024];     // hidden hi
__device__ __align__(16) __nv_bfloat16 g_alo[4096*1024];     // hidden lo
__device__ __align__(16) __nv_bfloat16 g_whi[4096*1024];     // Wq|Wk|Wv|Wo hi
__device__ __align__(16) __nv_bfloat16 g_wlo[4096*1024];
// t=0: Q fp16 single (hi slot); t=1: K fp16 hi/lo; t=2: V fp16 single (hi slot)
__device__ __align__(16) __nv_bfloat16 g_qkv_hi[3*4194304];
__device__ __align__(16) __nv_bfloat16 g_qkv_lo[3*4194304];
__device__ __align__(16) __nv_bfloat16 g_ctx_hi[4096*1024];  // ctx [b*s][h*dk]
__device__ __align__(16) __nv_bfloat16 g_ctx_lo[4096*1024];

// ================= PTX helpers (baseline ISA only) =================
__device__ __forceinline__ uint32_t smem_u32(const void* p) {
    uint32_t a;
    asm("{ .reg .u64 t; cvta.to.shared.u64 t, %1; cvt.u32.u64 %0, t; }"
        : "=r"(a) : "l"(p));
    return a;
}

#define CP_ASYNC16(sa, ga) \
    asm volatile("cp.async.cg.shared.global [%0], [%1], 16;" \
        :: "r"(sa), "l"(ga) : "memory")
#define CP_COMMIT() asm volatile("cp.async.commit_group;" ::: "memory")
#define CP_WAIT1()  asm volatile("cp.async.wait_group 1;" ::: "memory")
#define CP_WAIT0()  asm volatile("cp.async.wait_group 0;" ::: "memory")

__device__ __forceinline__ void ldsm4(uint32_t addr, uint32_t& r0, uint32_t& r1,
                                      uint32_t& r2, uint32_t& r3) {
    asm volatile("ldmatrix.sync.aligned.m8n8.x4.shared.b16 {%0,%1,%2,%3}, [%4];"
        : "=r"(r0), "=r"(r1), "=r"(r2), "=r"(r3) : "r"(addr));
}
__device__ __forceinline__ void ldsm4t(uint32_t addr, uint32_t& r0, uint32_t& r1,
                                       uint32_t& r2, uint32_t& r3) {
    asm volatile("ldmatrix.sync.aligned.m8n8.x4.trans.shared.b16 {%0,%1,%2,%3}, [%4];"
        : "=r"(r0), "=r"(r1), "=r"(r2), "=r"(r3) : "r"(addr));
}

__device__ __forceinline__ void mma16816(float* d, const uint32_t* a,
                                         uint32_t b0, uint32_t b1) {
    asm volatile("mma.sync.aligned.m16n8k16.row.col.f32.bf16.bf16.f32 "
        "{%0,%1,%2,%3}, {%4,%5,%6,%7}, {%8,%9}, {%0,%1,%2,%3};"
        : "+f"(d[0]), "+f"(d[1]), "+f"(d[2]), "+f"(d[3])
        : "r"(a[0]), "r"(a[1]), "r"(a[2]), "r"(a[3]), "r"(b0), "r"(b1));
}
__device__ __forceinline__ void mma16816h(float* d, const uint32_t* a,
                                          uint32_t b0, uint32_t b1) {
    asm volatile("mma.sync.aligned.m16n8k16.row.col.f32.f16.f16.f32 "
        "{%0,%1,%2,%3}, {%4,%5,%6,%7}, {%8,%9}, {%0,%1,%2,%3};"
        : "+f"(d[0]), "+f"(d[1]), "+f"(d[2]), "+f"(d[3])
        : "r"(a[0]), "r"(a[1]), "r"(a[2]), "r"(a[3]), "r"(b0), "r"(b1));
}

__device__ __forceinline__ void split2(float x0, float x1, uint32_t& hi, uint32_t& lo) {
    __nv_bfloat16 h0 = __float2bfloat16(x0);
    __nv_bfloat16 h1 = __float2bfloat16(x1);
    __nv_bfloat162 th; th.x = h0; th.y = h1;
    hi = *(uint32_t*)&th;
    __nv_bfloat162 tl;
    tl.x = __float2bfloat16(x0 - __bfloat162float(h0));
    tl.y = __float2bfloat16(x1 - __bfloat162float(h1));
    lo = *(uint32_t*)&tl;
}
__device__ __forceinline__ void split2h(float x0, float x1, uint32_t& hi, uint32_t& lo) {
    __half h0 = __float2half_rn(x0);
    __half h1 = __float2half_rn(x1);
    __half2 th = __halves2half2(h0, h1);
    hi = *(uint32_t*)&th;
    __half2 tl = __halves2half2(__float2half_rn(x0 - __half2float(h0)),
                                __float2half_rn(x1 - __half2float(h1)));
    lo = *(uint32_t*)&tl;
}

// ------------------------------------------------------------------
// One kernel: split hidden (4M) + all four weights (4M)
// ------------------------------------------------------------------
__global__ void split_all_kernel(const float* __restrict__ hid,
                                 const float* __restrict__ w0, const float* __restrict__ w1,
                                 const float* __restrict__ w2, const float* __restrict__ w3,
                                 __nv_bfloat16* __restrict__ ahi, __nv_bfloat16* __restrict__ alo,
                                 __nv_bfloat16* __restrict__ whi, __nv_bfloat16* __restrict__ wlo) {
    int i = blockIdx.x * blockDim.x + threadIdx.x;   // 0..8M-1
    float v;
    __nv_bfloat16* hi;
    __nv_bfloat16* lo;
    int dst;
    if (i < 4194304) {
        v = hid[i];
        hi = ahi; lo = alo; dst = i;
    } else {
        int j = i - 4194304;
        int t = j >> 20;
        int off = j & 1048575;
        const float* src = (t == 0) ? w0 : (t == 1) ? w1 : (t == 2) ? w2 : w3;
        v = src[off];
        hi = whi; lo = wlo; dst = j;
    }
    __nv_bfloat16 h = __float2bfloat16(v);
    hi[dst] = h;
    lo[dst] = __float2bfloat16(v - __bfloat162float(h));
}

// ------------------------------------------------------------------
__global__ void bias_kernel(const float* __restrict__ rel_bias) {
    int idx = blockIdx.x * blockDim.x + threadIdx.x;
    const int total = (2*SS-1)*HH;
    if (idx >= total) return;
    int d = idx / HH;
    int h = idx - d*HH;
    int rp = d - (SS - 1);
    int rb = (rp > 0) ? 16 : 0;
    int n = rp < 0 ? -rp : rp;
    int b;
    if (n < 8) {
        b = n;
    } else {
        double v = log((double)n / 8.0) / log(16.0) * 8.0;
        int large = 8 + (int)v;
        b = large < 15 ? large : 15;
    }
    g_bias[idx] = rel_bias[(rb + b)*HH + h];
}

// ------------------------------------------------------------------
// HMMA bf16x3 GEMM. mode 0: fp32 row-major out.
// mode 2: QKV fused; Q (t=0) fp16 single; K (t=1) fp16 hi/lo; V (t=2) fp16 single.
// ------------------------------------------------------------------
#define BKG 32
#define STAGES 3
#define TENSOR_BYTES (128*64)
#define STAGE_BYTES  (4*TENSOR_BYTES)
#define GEMM_SMEM    (STAGES*STAGE_BYTES)

__global__ void __launch_bounds__(256, 2) gemm_mma_kernel(
    const __nv_bfloat16* __restrict__ Ahi, const __nv_bfloat16* __restrict__ Alo,
    const __nv_bfloat16* __restrict__ Whi, const __nv_bfloat16* __restrict__ Wlo,
    float* __restrict__ C,
    __nv_bfloat16* __restrict__ Chi, __nv_bfloat16* __restrict__ Clo,
    int mode)
{
    extern __shared__ __align__(128) char smem[];
    const uint32_t sb = smem_u32(smem);
    const int tid  = threadIdx.x;
    const int warp = tid >> 5, lane = tid & 31;
    const int wm = warp >> 2, wn = warp & 3;
    const int nt = blockIdx.x, mt = blockIdx.y;

    const __nv_bfloat16* src0 = Ahi + (size_t)(mt*128)*1024;
    const __nv_bfloat16* src1 = Alo + (size_t)(mt*128)*1024;
    const __nv_bfloat16* src2 = Whi + (size_t)(nt*128)*1024;
    const __nv_bfloat16* src3 = Wlo + (size_t)(nt*128)*1024;
    const __nv_bfloat16* mysrc = (tid < 64) ? src0 : (tid < 128) ? src1
                               : (tid < 192) ? src2 : src3;
    const int t4 = tid >> 6;
    const int li = tid & 63;

    #define ISSUE(it) do { \
        int _stg = (it) % STAGES; \
        uint32_t _sbase = sb + _stg*STAGE_BYTES + t4*TENSOR_BYTES; \
        const __nv_bfloat16* _g = mysrc + (it)*BKG; \
        _Pragma("unroll") \
        for (int _j = 0; _j < 8; _j++) { \
            int _ch = li + _j*64; \
            int _r = _ch >> 2, _c = _ch & 3; \
            int _cs = _c ^ ((_r >> 1) & 3); \
            CP_ASYNC16(_sbase + _r*64 + _cs*16, _g + (size_t)_r*1024 + _c*8); \
        } \
    } while (0)

    ISSUE(0); CP_COMMIT();
    ISSUE(1); CP_COMMIT();

    float acc[4][4][4];
    #pragma unroll
    for (int i = 0; i < 4; i++)
        #pragma unroll
        for (int j = 0; j < 4; j++)
            #pragma unroll
            for (int q = 0; q < 4; q++) acc[i][j][q] = 0.f;

    const int arow = lane & 15;
    const int asel = lane >> 4;
    const int brow = ((lane >> 4) << 3) | (lane & 7);
    const int bsel = (lane >> 3) & 1;

    for (int it = 0; it < 32; it++) {
        CP_WAIT1();
        __syncthreads();
        if (it + 2 < 32) ISSUE(it + 2);
        CP_COMMIT();

        const uint32_t st = sb + (it % STAGES)*STAGE_BYTES;
        #pragma unroll
        for (int ks = 0; ks < 2; ks++) {
            uint32_t ah[4][4], al[4][4];
            #pragma unroll
            for (int mi = 0; mi < 4; mi++) {
                int r = wm*64 + mi*16 + arow;
                int c = 2*ks + asel;
                uint32_t off = (uint32_t)(r*64 + ((c ^ ((r>>1)&3))*16));
                ldsm4(st + off,               ah[mi][0], ah[mi][1], ah[mi][2], ah[mi][3]);
                ldsm4(st + TENSOR_BYTES + off, al[mi][0], al[mi][1], al[mi][2], al[mi][3]);
            }
            uint32_t bh2[2][4], bl2[2][4];
            #pragma unroll
            for (int np = 0; np < 2; np++) {
                int r = wn*32 + np*16 + brow;
                int c = 2*ks + bsel;
                uint32_t off = (uint32_t)(r*64 + ((c ^ ((r>>1)&3))*16));
                ldsm4(st + 2*TENSOR_BYTES + off, bh2[np][0], bh2[np][1], bh2[np][2], bh2[np][3]);
                ldsm4(st + 3*TENSOR_BYTES + off, bl2[np][0], bl2[np][1], bl2[np][2], bl2[np][3]);
            }
            #pragma unroll
            for (int mi = 0; mi < 4; mi++)
                #pragma unroll
                for (int ni = 0; ni < 4; ni++) {
                    uint32_t b0h = bh2[ni>>1][(ni&1)*2], b1h = bh2[ni>>1][(ni&1)*2+1];
                    uint32_t b0l = bl2[ni>>1][(ni&1)*2], b1l = bl2[ni>>1][(ni&1)*2+1];
                    mma16816(acc[mi][ni], ah[mi], b0h, b1h);
                    mma16816(acc[mi][ni], ah[mi], b0l, b1l);
                    mma16816(acc[mi][ni], al[mi], b0h, b1h);
                }
        }
    }
    #undef ISSUE

    const int lrow = lane >> 2;
    const int lcol = (lane & 3)*2;
    if (mode == 0) {
        const int mrow0 = mt*128 + wm*64;
        const int ncol0 = nt*128 + wn*32;
        #pragma unroll
        for (int mi = 0; mi < 4; mi++)
            #pragma unroll
            for (int ni = 0; ni < 4; ni++) {
                int m0 = mrow0 + mi*16 + lrow;
                int n0 = ncol0 + ni*8 + lcol;
                *(float2*)(C + (size_t)m0*1024 + n0) =
                    make_float2(acc[mi][ni][0], acc[mi][ni][1]);
                *(float2*)(C + (size_t)(m0+8)*1024 + n0) =
                    make_float2(acc[mi][ni][2], acc[mi][ni][3]);
            }
    } else {
        const int t = nt >> 3;
        const size_t tbase = (size_t)t * 4194304;
        const int mrow0 = mt*128 + wm*64;
        const int ncol0 = (nt & 7)*128 + wn*32;
        #pragma unroll
        for (int mi = 0; mi < 4; mi++)
            #pragma unroll
            for (int ni = 0; ni < 4; ni++) {
                int m0 = mrow0 + mi*16 + lrow;
                int m1 = m0 + 8;
                int n0 = ncol0 + ni*8 + lcol;
                int h = n0 >> 6, dk = n0 & 63;
                int b0 = m0 >> 10, s0 = m0 & 1023;
                int b1 = m1 >> 10, s1 = m1 & 1023;
                size_t i0 = tbase + ((size_t)((b0*HH + h)*SS + s0))*DKK + dk;
                size_t i1 = tbase + ((size_t)((b1*HH + h)*SS + s1))*DKK + dk;
                if (t == 1) {   // K: fp16 hi/lo
                    uint32_t hi, lo;
                    split2h(acc[mi][ni][0], acc[mi][ni][1], hi, lo);
                    *(uint32_t*)&Chi[i0] = hi;
                    *(uint32_t*)&Clo[i0] = lo;
                    split2h(acc[mi][ni][2], acc[mi][ni][3], hi, lo);
                    *(uint32_t*)&Chi[i1] = hi;
                    *(uint32_t*)&Clo[i1] = lo;
                } else {        // Q, V: fp16 single
                    __half2 t0 = __floats2half2_rn(acc[mi][ni][0], acc[mi][ni][1]);
                    *(uint32_t*)&Chi[i0] = *(uint32_t*)&t0;
                    __half2 t1 = __floats2half2_rn(acc[mi][ni][2], acc[mi][ni][3]);
                    *(uint32_t*)&Chi[i1] = *(uint32_t*)&t1;
                }
            }
    }
}

// ------------------------------------------------------------------
// Fused flash attention, all-fp16 MMAs:
// QK^T = Qf·Kh + Qf·Kl (2 MMAs), PV = P·Vf (1 MMA pair). Online softmax.
// smem: Q 16K + 2 stages x 3x16K + bias 8K = 120K.
// ------------------------------------------------------------------
#define T16 16384
#define FS_Q 0
#define FS_ST0 (T16)
#define FS_ST1 (4*T16)
#define FS_BIAS (7*T16)
#define FLASH_SMEM (7*T16 + 8192)

#define SWZ(r, c) ((uint32_t)((r)*128 + (((c) ^ ((r)&7))*16)))

__global__ void __launch_bounds__(256, 1) flash_kernel() {
    extern __shared__ __align__(128) char smem[];
    const uint32_t sb = smem_u32(smem);
    float* bias_all = (float*)(smem + FS_BIAS);   // [8][256]

    const int tid  = threadIdx.x;
    const int w = tid >> 5, lane = tid & 31;
    const int mbase = blockIdx.x * 128;
    const int bh = blockIdx.y;
    const int b = bh >> 4, h = bh & 15;

    const size_t base = (size_t)bh*SS*DKK;
    const __nv_bfloat16* Qf = g_qkv_hi + base + (size_t)mbase*DKK;     // fp16 bits
    const __nv_bfloat16* Kh = g_qkv_hi + 4194304 + base;               // fp16 bits
    const __nv_bfloat16* Kl = g_qkv_lo + 4194304 + base;               // fp16 bits
    const __nv_bfloat16* Vf = g_qkv_hi + 8388608 + base;               // fp16 bits

    #pragma unroll
    for (int i = 0; i < 4; i++) {
        int id = tid + i*256;
        int r = id >> 3, c = id & 7;
        uint32_t off = SWZ(r, c);
        CP_ASYNC16(sb + FS_Q + off, Qf + (size_t)r*64 + c*8);
    }
    #define ISSUE_KV(j, stoff) do { \
        const size_t _jo = (size_t)(j)*128*64; \
        _Pragma("unroll") \
        for (int _i = 0; _i < 4; _i++) { \
            int _id = tid + _i*256; \
            int _r = _id >> 3, _c = _id & 7; \
            uint32_t _off = SWZ(_r, _c); \
            const size_t _go = _jo + (size_t)_r*64 + _c*8; \
            CP_ASYNC16(sb + (stoff) + 0*T16 + _off, Kh + _go); \
            CP_ASYNC16(sb + (stoff) + 1*T16 + _off, Kl + _go); \
            CP_ASYNC16(sb + (stoff) + 2*T16 + _off, Vf + _go); \
        } \
    } while (0)
    ISSUE_KV(0, FS_ST0); CP_COMMIT();
    ISSUE_KV(1, FS_ST1); CP_COMMIT();

    // preload ALL bias windows while cp.async is in flight
    for (int t = tid; t < 8*255; t += 256) {
        int jj = t / 255;
        int tt = t - jj*255;
        bias_all[jj*256 + tt] =
            g_bias[(size_t)(jj*128 - mbase + tt - 127 + (SS-1))*HH + h];
    }

    float Oacc[8][4];
    #pragma unroll
    for (int d = 0; d < 8; d++)
        #pragma unroll
        for (int q = 0; q < 4; q++) Oacc[d][q] = 0.f;
    float mrun0 = -1e30f, mrun1 = -1e30f, lrun0 = 0.f, lrun1 = 0.f;

    const int r0 = lane >> 2;
    const int colb = (lane & 3)*2;
    const int rl0 = w*16 + r0;
    const int rl1 = rl0 + 8;

    const int a_r = w*16 + (lane & 15);
    const int a_s = lane >> 4;
    const int b_r = ((lane >> 4) << 3) | (lane & 7);
    const int b_s = (lane >> 3) & 1;
    const int v_k = ((lane >> 3) & 1)*8 + (lane & 7);
    const int v_c = lane >> 4;

    CP_WAIT1();
    __syncthreads();
    uint32_t qf[4][4];
    #pragma unroll
    for (int ks = 0; ks < 4; ks++) {
        uint32_t aoff = SWZ(a_r, 2*ks + a_s);
        ldsm4(sb + FS_Q + aoff, qf[ks][0], qf[ks][1], qf[ks][2], qf[ks][3]);
    }

    for (int j = 0; j < 8; j++) {
        if (j > 0) {
            if (j < 7) { CP_WAIT1(); } else { CP_WAIT0(); }
            __syncthreads();
        }

        const uint32_t st = sb + ((j & 1) ? FS_ST1 : FS_ST0);
        const float* bias_s = bias_all + j*256;

        // ---- S = Q K^T (fp16: Qf x (Kh + Kl)) ----
        float sacc[16][4];
        #pragma unroll
        for (int nt = 0; nt < 16; nt++)
            #pragma unroll
            for (int q = 0; q < 4; q++) sacc[nt][q] = 0.f;

        #pragma unroll
        for (int ks = 0; ks < 4; ks++) {
            #pragma unroll
            for (int np = 0; np < 8; np++) {
                uint32_t kh[4], kl[4];
                uint32_t boff = SWZ(np*16 + b_r, 2*ks + b_s);
                ldsm4(st + 0*T16 + boff, kh[0], kh[1], kh[2], kh[3]);
                ldsm4(st + 1*T16 + boff, kl[0], kl[1], kl[2], kl[3]);
                mma16816h(sacc[2*np],   qf[ks], kh[0], kh[1]);
                mma16816h(sacc[2*np],   qf[ks], kl[0], kl[1]);
                mma16816h(sacc[2*np+1], qf[ks], kh[2], kh[3]);
                mma16816h(sacc[2*np+1], qf[ks], kl[2], kl[3]);
            }
        }

        // ---- bias ----
        #pragma unroll
        for (int nt = 0; nt < 16; nt++) {
            int col = nt*8 + colb;
            sacc[nt][0] += bias_s[col     - rl0 + 127];
            sacc[nt][1] += bias_s[col + 1 - rl0 + 127];
            sacc[nt][2] += bias_s[col     - rl1 + 127];
            sacc[nt][3] += bias_s[col + 1 - rl1 + 127];
        }

        // ---- online softmax ----
        float mx0 = -1e30f, mx1 = -1e30f;
        #pragma unroll
        for (int nt = 0; nt < 16; nt++) {
            mx0 = fmaxf(mx0, fmaxf(sacc[nt][0], sacc[nt][1]));
            mx1 = fmaxf(mx1, fmaxf(sacc[nt][2], sacc[nt][3]));
        }
        mx0 = fmaxf(mx0, __shfl_xor_sync(0xffffffffu, mx0, 1));
        mx0 = fmaxf(mx0, __shfl_xor_sync(0xffffffffu, mx0, 2));
        mx1 = fmaxf(mx1, __shfl_xor_sync(0xffffffffu, mx1, 1));
        mx1 = fmaxf(mx1, __shfl_xor_sync(0xffffffffu, mx1, 2));

        float mn0 = fmaxf(mrun0, mx0);
        float mn1 = fmaxf(mrun1, mx1);
        float al0 = __expf(mrun0 - mn0);
        float al1 = __expf(mrun1 - mn1);
        mrun0 = mn0; mrun1 = mn1;

        float rs0 = 0.f, rs1 = 0.f;
        #pragma unroll
        for (int nt = 0; nt < 16; nt++) {
            sacc[nt][0] = __expf(sacc[nt][0] - mn0);
            sacc[nt][1] = __expf(sacc[nt][1] - mn0);
            sacc[nt][2] = __expf(sacc[nt][2] - mn1);
            sacc[nt][3] = __expf(sacc[nt][3] - mn1);
            rs0 += sacc[nt][0] + sacc[nt][1];
            rs1 += sacc[nt][2] + sacc[nt][3];
        }
        rs0 += __shfl_xor_sync(0xffffffffu, rs0, 1);
        rs0 += __shfl_xor_sync(0xffffffffu, rs0, 2);
        rs1 += __shfl_xor_sync(0xffffffffu, rs1, 1);
        rs1 += __shfl_xor_sync(0xffffffffu, rs1, 2);
        lrun0 = lrun0*al0 + rs0;
        lrun1 = lrun1*al1 + rs1;

        #pragma unroll
        for (int d = 0; d < 8; d++) {
            Oacc[d][0] *= al0; Oacc[d][1] *= al0;
            Oacc[d][2] *= al1; Oacc[d][3] *= al1;
        }

        // ---- O += P V (fp16 single both) ----
        #pragma unroll
        for (int ks = 0; ks < 8; ks++) {
            uint32_t ph[4];
            {
                __half2 t0 = __floats2half2_rn(sacc[2*ks][0],   sacc[2*ks][1]);
                __half2 t1 = __floats2half2_rn(sacc[2*ks][2],   sacc[2*ks][3]);
                __half2 t2 = __floats2half2_rn(sacc[2*ks+1][0], sacc[2*ks+1][1]);
                __half2 t3 = __floats2half2_rn(sacc[2*ks+1][2], sacc[2*ks+1][3]);
                ph[0] = *(uint32_t*)&t0;
                ph[1] = *(uint32_t*)&t1;
                ph[2] = *(uint32_t*)&t2;
                ph[3] = *(uint32_t*)&t3;
            }
            #pragma unroll
            for (int dp = 0; dp < 4; dp++) {
                uint32_t vh[4];
                uint32_t voff = SWZ(ks*16 + v_k, dp*2 + v_c);
                ldsm4t(st + 2*T16 + voff, vh[0], vh[1], vh[2], vh[3]);
                mma16816h(Oacc[2*dp],   ph, vh[0], vh[1]);
                mma16816h(Oacc[2*dp+1], ph, vh[2], vh[3]);
            }
        }

        __syncthreads();
        if (j + 2 < 8) {
            ISSUE_KV(j + 2, ((j & 1) ? FS_ST1 : FS_ST0));
            CP_COMMIT();
        }
    }
    #undef ISSUE_KV

    // ---- epilogue: normalize + write ctx as bf16 hi/lo ----
    float inv0 = 1.0f / lrun0;
    float inv1 = 1.0f / lrun1;
    int m0 = mbase + rl0;
    int m1 = mbase + rl1;
    #pragma unroll
    for (int dt = 0; dt < 8; dt++) {
        int d = dt*8 + colb;
        size_t i0 = ((size_t)(b*SS + m0))*DD + h*DKK + d;
        size_t i1 = ((size_t)(b*SS + m1))*DD + h*DKK + d;
        uint32_t hi, lo;
        split2(Oacc[dt][0]*inv0, Oacc[dt][1]*inv0, hi, lo);
        *(uint32_t*)&g_ctx_hi[i0] = hi;
        *(uint32_t*)&g_ctx_lo[i0] = lo;
        split2(Oacc[dt][2]*inv1, Oacc[dt][3]*inv1, hi, lo);
        *(uint32_t*)&g_ctx_hi[i1] = hi;
        *(uint32_t*)&g_ctx_lo[i1] = lo;
    }
}

// ------------------------------------------------------------------
extern "C" void kernel_launch(void* const* d_in, const int* in_sizes, int n_in,
                              void* d_out, int out_size) {
    const float* hidden   = (const float*)d_in[0];
    const float* Wq       = (const float*)d_in[1];
    const float* Wk       = (const float*)d_in[2];
    const float* Wv       = (const float*)d_in[3];
    const float* Wo       = (const float*)d_in[4];
    const float* rel_bias = (const float*)d_in[5];
    float* out = (float*)d_out;

    __nv_bfloat16 *pahi, *palo, *pwhi, *pwlo, *pqkvh, *pqkvl, *pchi, *pclo;
    cudaGetSymbolAddress((void**)&pahi, g_ahi);
    cudaGetSymbolAddress((void**)&palo, g_alo);
    cudaGetSymbolAddress((void**)&pwhi, g_whi);
    cudaGetSymbolAddress((void**)&pwlo, g_wlo);
    cudaGetSymbolAddress((void**)&pqkvh, g_qkv_hi);
    cudaGetSymbolAddress((void**)&pqkvl, g_qkv_lo);
    cudaGetSymbolAddress((void**)&pchi, g_ctx_hi);
    cudaGetSymbolAddress((void**)&pclo, g_ctx_lo);

    cudaFuncSetAttribute(gemm_mma_kernel,
                         cudaFuncAttributeMaxDynamicSharedMemorySize, GEMM_SMEM);
    cudaFuncSetAttribute(flash_kernel,
                         cudaFuncAttributeMaxDynamicSharedMemorySize, FLASH_SMEM);

    bias_kernel<<<((2*SS-1)*HH + 255)/256, 256>>>(rel_bias);
    split_all_kernel<<<(8388608 + 255)/256, 256>>>(
        hidden, Wq, Wk, Wv, Wo, pahi, palo, pwhi, pwlo);

    // fused QKV projection -> Q fp16; K fp16 hi/lo; V fp16
    gemm_mma_kernel<<<dim3(24, 32), 256, GEMM_SMEM>>>(
        pahi, palo, pwhi, pwlo, nullptr, pqkvh, pqkvl, 2);

    // fused attention
    flash_kernel<<<dim3(8, BH), 256, FLASH_SMEM>>>();

    // output projection (fp32 out)
    gemm_mma_kernel<<<dim3(8, 32), 256, GEMM_SMEM>>>(
        pchi, pclo, pwhi + 3145728, pwlo + 3145728, out, nullptr, nullptr, 0);
}

// round 15
// speedup vs baseline: 2.0020x; 1.1135x over previous
#include <cuda_runtime.h>
#include <cuda_bf16.h>
#include <cuda_fp16.h>
#include <math.h>
#include <stdint.h>

#define BB 4
#define SS 1024
#define DD 1024
#define HH 16
#define DKK 64
#define BH (BB*HH)

// ---- scratch (device globals; no allocation allowed) ----
__device__ float g_bias[(2*SS-1)*HH];          // pre-scaled by log2(e)

__device__ __align__(16) __nv_bfloat16 g_ahi[4096*1024];     // hidden hi (bf16)
__device__ __align__(16) __nv_bfloat16 g_alo[4096*1024];     // hidden lo (bf16)
// Wq|Wk|Wv bf16 hi/lo; Wo slot (rows 3M..4M) holds fp16 hi/lo
__device__ __align__(16) __nv_bfloat16 g_whi[4096*1024];
__device__ __align__(16) __nv_bfloat16 g_wlo[4096*1024];
// q|k|v all single fp16 (q pre-scaled by log2e)  [t][bh][s][dk]
__device__ __align__(16) __nv_bfloat16 g_qkv[3*4194304];
__device__ __align__(16) __nv_bfloat16 g_ctx[4096*1024];     // ctx fp16 [b*s][h*dk]

// ================= PTX helpers (baseline ISA only) =================
__device__ __forceinline__ uint32_t smem_u32(const void* p) {
    uint32_t a;
    asm("{ .reg .u64 t; cvta.to.shared.u64 t, %1; cvt.u32.u64 %0, t; }"
        : "=r"(a) : "l"(p));
    return a;
}

#define CP_ASYNC16(sa, ga) \
    asm volatile("cp.async.cg.shared.global [%0], [%1], 16;" \
        :: "r"(sa), "l"(ga) : "memory")
#define CP_COMMIT() asm volatile("cp.async.commit_group;" ::: "memory")
#define CP_WAIT1()  asm volatile("cp.async.wait_group 1;" ::: "memory")
#define CP_WAIT0()  asm volatile("cp.async.wait_group 0;" ::: "memory")

__device__ __forceinline__ void ldsm4(uint32_t addr, uint32_t& r0, uint32_t& r1,
                                      uint32_t& r2, uint32_t& r3) {
    asm volatile("ldmatrix.sync.aligned.m8n8.x4.shared.b16 {%0,%1,%2,%3}, [%4];"
        : "=r"(r0), "=r"(r1), "=r"(r2), "=r"(r3) : "r"(addr));
}
__device__ __forceinline__ void ldsm4t(uint32_t addr, uint32_t& r0, uint32_t& r1,
                                       uint32_t& r2, uint32_t& r3) {
    asm volatile("ldmatrix.sync.aligned.m8n8.x4.trans.shared.b16 {%0,%1,%2,%3}, [%4];"
        : "=r"(r0), "=r"(r1), "=r"(r2), "=r"(r3) : "r"(addr));
}

__device__ __forceinline__ void mma16816(float* d, const uint32_t* a,
                                         uint32_t b0, uint32_t b1) {
    asm volatile("mma.sync.aligned.m16n8k16.row.col.f32.bf16.bf16.f32 "
        "{%0,%1,%2,%3}, {%4,%5,%6,%7}, {%8,%9}, {%0,%1,%2,%3};"
        : "+f"(d[0]), "+f"(d[1]), "+f"(d[2]), "+f"(d[3])
        : "r"(a[0]), "r"(a[1]), "r"(a[2]), "r"(a[3]), "r"(b0), "r"(b1));
}
__device__ __forceinline__ void mma16816h(float* d, const uint32_t* a,
                                          uint32_t b0, uint32_t b1) {
    asm volatile("mma.sync.aligned.m16n8k16.row.col.f32.f16.f16.f32 "
        "{%0,%1,%2,%3}, {%4,%5,%6,%7}, {%8,%9}, {%0,%1,%2,%3};"
        : "+f"(d[0]), "+f"(d[1]), "+f"(d[2]), "+f"(d[3])
        : "r"(a[0]), "r"(a[1]), "r"(a[2]), "r"(a[3]), "r"(b0), "r"(b1));
}

__device__ __forceinline__ float fast_exp2(float x) {
    float r;
    asm("ex2.approx.f32 %0, %1;" : "=f"(r) : "f"(x));
    return r;
}

// ------------------------------------------------------------------
// split hidden (bf16 hi/lo) + Wq/Wk/Wv (bf16 hi/lo) + Wo (fp16 hi/lo)
// ------------------------------------------------------------------
__global__ void split_all_kernel(const float* __restrict__ hid,
                                 const float* __restrict__ w0, const float* __restrict__ w1,
                                 const float* __restrict__ w2, const float* __restrict__ w3,
                                 __nv_bfloat16* __restrict__ ahi, __nv_bfloat16* __restrict__ alo,
                                 __nv_bfloat16* __restrict__ whi, __nv_bfloat16* __restrict__ wlo) {
    int i = blockIdx.x * blockDim.x + threadIdx.x;   // 0..8M-1
    if (i < 4194304) {
        float v = hid[i];
        __nv_bfloat16 h = __float2bfloat16(v);
        ahi[i] = h;
        alo[i] = __float2bfloat16(v - __bfloat162float(h));
    } else {
        int j = i - 4194304;
        int t = j >> 20;
        int off = j & 1048575;
        const float* src = (t == 0) ? w0 : (t == 1) ? w1 : (t == 2) ? w2 : w3;
        float v = src[off];
        if (t == 3) {   // Wo: fp16 hi/lo
            __half h = __float2half_rn(v);
            *(__half*)&whi[j] = h;
            *(__half*)&wlo[j] = __float2half_rn(v - __half2float(h));
        } else {        // bf16 hi/lo
            __nv_bfloat16 h = __float2bfloat16(v);
            whi[j] = h;
            wlo[j] = __float2bfloat16(v - __bfloat162float(h));
        }
    }
}

// ------------------------------------------------------------------
__global__ void bias_kernel(const float* __restrict__ rel_bias) {
    int idx = blockIdx.x * blockDim.x + threadIdx.x;
    const int total = (2*SS-1)*HH;
    if (idx >= total) return;
    int d = idx / HH;
    int h = idx - d*HH;
    int rp = d - (SS - 1);
    int rb = (rp > 0) ? 16 : 0;
    int n = rp < 0 ? -rp : rp;
    int b;
    if (n < 8) {
        b = n;
    } else {
        double v = log((double)n / 8.0) / log(16.0) * 8.0;
        int large = 8 + (int)v;
        b = large < 15 ? large : 15;
    }
    // store in log2 domain
    g_bias[idx] = (float)((double)rel_bias[(rb + b)*HH + h] * 1.4426950408889634);
}

// ------------------------------------------------------------------
// QKV GEMM (bf16x3): writes Q (x log2e), K, V as single fp16, head-split.
// grid (24, 32): nt>>3 = tensor, nt&7 = N tile.
// ------------------------------------------------------------------
#define BKG 32
#define STAGES 3
#define TENSOR_BYTES (128*64)
#define STAGE_BYTES  (4*TENSOR_BYTES)
#define GEMM_SMEM    (STAGES*STAGE_BYTES)

__global__ void __launch_bounds__(256, 2) gemm_qkv_kernel(
    const __nv_bfloat16* __restrict__ Ahi, const __nv_bfloat16* __restrict__ Alo,
    const __nv_bfloat16* __restrict__ Whi, const __nv_bfloat16* __restrict__ Wlo,
    __nv_bfloat16* __restrict__ Cq)
{
    extern __shared__ __align__(128) char smem[];
    const uint32_t sb = smem_u32(smem);
    const int tid  = threadIdx.x;
    const int warp = tid >> 5, lane = tid & 31;
    const int wm = warp >> 2, wn = warp & 3;
    const int nt = blockIdx.x, mt = blockIdx.y;

    const __nv_bfloat16* src0 = Ahi + (size_t)(mt*128)*1024;
    const __nv_bfloat16* src1 = Alo + (size_t)(mt*128)*1024;
    const __nv_bfloat16* src2 = Whi + (size_t)(nt*128)*1024;
    const __nv_bfloat16* src3 = Wlo + (size_t)(nt*128)*1024;
    const __nv_bfloat16* mysrc = (tid < 64) ? src0 : (tid < 128) ? src1
                               : (tid < 192) ? src2 : src3;
    const int t4 = tid >> 6;
    const int li = tid & 63;

    #define ISSUE(it) do { \
        int _stg = (it) % STAGES; \
        uint32_t _sbase = sb + _stg*STAGE_BYTES + t4*TENSOR_BYTES; \
        const __nv_bfloat16* _g = mysrc + (it)*BKG; \
        _Pragma("unroll") \
        for (int _j = 0; _j < 8; _j++) { \
            int _ch = li + _j*64; \
            int _r = _ch >> 2, _c = _ch & 3; \
            int _cs = _c ^ ((_r >> 1) & 3); \
            CP_ASYNC16(_sbase + _r*64 + _cs*16, _g + (size_t)_r*1024 + _c*8); \
        } \
    } while (0)

    ISSUE(0); CP_COMMIT();
    ISSUE(1); CP_COMMIT();

    float acc[4][4][4];
    #pragma unroll
    for (int i = 0; i < 4; i++)
        #pragma unroll
        for (int j = 0; j < 4; j++)
            #pragma unroll
            for (int q = 0; q < 4; q++) acc[i][j][q] = 0.f;

    const int arow = lane & 15;
    const int asel = lane >> 4;
    const int brow = ((lane >> 4) << 3) | (lane & 7);
    const int bsel = (lane >> 3) & 1;

    for (int it = 0; it < 32; it++) {
        CP_WAIT1();
        __syncthreads();
        if (it + 2 < 32) ISSUE(it + 2);
        CP_COMMIT();

        const uint32_t st = sb + (it % STAGES)*STAGE_BYTES;
        #pragma unroll
        for (int ks = 0; ks < 2; ks++) {
            uint32_t ah[4][4], al[4][4];
            #pragma unroll
            for (int mi = 0; mi < 4; mi++) {
                int r = wm*64 + mi*16 + arow;
                int c = 2*ks + asel;
                uint32_t off = (uint32_t)(r*64 + ((c ^ ((r>>1)&3))*16));
                ldsm4(st + off,               ah[mi][0], ah[mi][1], ah[mi][2], ah[mi][3]);
                ldsm4(st + TENSOR_BYTES + off, al[mi][0], al[mi][1], al[mi][2], al[mi][3]);
            }
            uint32_t bh2[2][4], bl2[2][4];
            #pragma unroll
            for (int np = 0; np < 2; np++) {
                int r = wn*32 + np*16 + brow;
                int c = 2*ks + bsel;
                uint32_t off = (uint32_t)(r*64 + ((c ^ ((r>>1)&3))*16));
                ldsm4(st + 2*TENSOR_BYTES + off, bh2[np][0], bh2[np][1], bh2[np][2], bh2[np][3]);
                ldsm4(st + 3*TENSOR_BYTES + off, bl2[np][0], bl2[np][1], bl2[np][2], bl2[np][3]);
            }
            #pragma unroll
            for (int mi = 0; mi < 4; mi++)
                #pragma unroll
                for (int ni = 0; ni < 4; ni++) {
                    uint32_t b0h = bh2[ni>>1][(ni&1)*2], b1h = bh2[ni>>1][(ni&1)*2+1];
                    uint32_t b0l = bl2[ni>>1][(ni&1)*2], b1l = bl2[ni>>1][(ni&1)*2+1];
                    mma16816(acc[mi][ni], ah[mi], b0h, b1h);
                    mma16816(acc[mi][ni], ah[mi], b0l, b1l);
                    mma16816(acc[mi][ni], al[mi], b0h, b1h);
                }
        }
    }
    #undef ISSUE

    const int lrow = lane >> 2;
    const int lcol = (lane & 3)*2;
    const int t = nt >> 3;
    const float scl = (t == 0) ? 1.44269504f : 1.0f;   // Q in log2 domain
    const size_t tbase = (size_t)t * 4194304;
    const int mrow0 = mt*128 + wm*64;
    const int ncol0 = (nt & 7)*128 + wn*32;
    #pragma unroll
    for (int mi = 0; mi < 4; mi++)
        #pragma unroll
        for (int ni = 0; ni < 4; ni++) {
            int m0 = mrow0 + mi*16 + lrow;
            int m1 = m0 + 8;
            int n0 = ncol0 + ni*8 + lcol;
            int h = n0 >> 6, dk = n0 & 63;
            int b0 = m0 >> 10, s0 = m0 & 1023;
            int b1 = m1 >> 10, s1 = m1 & 1023;
            size_t i0 = tbase + ((size_t)((b0*HH + h)*SS + s0))*DKK + dk;
            size_t i1 = tbase + ((size_t)((b1*HH + h)*SS + s1))*DKK + dk;
            __half2 h0 = __floats2half2_rn(acc[mi][ni][0]*scl, acc[mi][ni][1]*scl);
            *(uint32_t*)&g_qkv[i0] = *(uint32_t*)&h0;
            __half2 h1 = __floats2half2_rn(acc[mi][ni][2]*scl, acc[mi][ni][3]*scl);
            *(uint32_t*)&g_qkv[i1] = *(uint32_t*)&h1;
        }
}

// ------------------------------------------------------------------
// Out projection: C[m,n] = sum_k ctx_f[m,k] * (Woh+Wol)[n,k], fp16 2-MMA.
// ------------------------------------------------------------------
#define OUT_TB 8192
#define OUT_STAGE (3*OUT_TB)
#define OUT_SMEM (STAGES*OUT_STAGE)

__global__ void __launch_bounds__(256, 2) gemm_out_kernel(
    const __nv_bfloat16* __restrict__ Af,    // fp16 bits
    const __nv_bfloat16* __restrict__ Whi,   // fp16 bits
    const __nv_bfloat16* __restrict__ Wlo,   // fp16 bits
    float* __restrict__ C)
{
    extern __shared__ __align__(128) char smem[];
    const uint32_t sb = smem_u32(smem);
    const int tid  = threadIdx.x;
    const int warp = tid >> 5, lane = tid & 31;
    const int wm = warp >> 2, wn = warp & 3;
    const int nt = blockIdx.x, mt = blockIdx.y;

    const __nv_bfloat16* srcA = Af  + (size_t)(mt*128)*1024;
    const __nv_bfloat16* srcH = Whi + (size_t)(nt*128)*1024;
    const __nv_bfloat16* srcL = Wlo + (size_t)(nt*128)*1024;

    #define OISSUE(it) do { \
        int _stg = (it) % STAGES; \
        uint32_t _sbase = sb + _stg*OUT_STAGE; \
        _Pragma("unroll") \
        for (int _k = 0; _k < 6; _k++) { \
            int _c0 = tid + _k*256; \
            int _t = _c0 >> 9; \
            int _idx = _c0 & 511; \
            int _r = _idx >> 2, _cc = _idx & 3; \
            int _cs = _cc ^ ((_r >> 1) & 3); \
            const __nv_bfloat16* _g = ((_t == 0) ? srcA : (_t == 1) ? srcH : srcL) \
                                      + (it)*BKG; \
            CP_ASYNC16(_sbase + _t*OUT_TB + _r*64 + _cs*16, \
                       _g + (size_t)_r*1024 + _cc*8); \
        } \
    } while (0)

    OISSUE(0); CP_COMMIT();
    OISSUE(1); CP_COMMIT();

    float acc[4][4][4];
    #pragma unroll
    for (int i = 0; i < 4; i++)
        #pragma unroll
        for (int j = 0; j < 4; j++)
            #pragma unroll
            for (int q = 0; q < 4; q++) acc[i][j][q] = 0.f;

    const int arow = lane & 15;
    const int asel = lane >> 4;
    const int brow = ((lane >> 4) << 3) | (lane & 7);
    const int bsel = (lane >> 3) & 1;

    for (int it = 0; it < 32; it++) {
        CP_WAIT1();
        __syncthreads();
        if (it + 2 < 32) OISSUE(it + 2);
        CP_COMMIT();

        const uint32_t st = sb + (it % STAGES)*OUT_STAGE;
        #pragma unroll
        for (int ks = 0; ks < 2; ks++) {
            uint32_t af[4][4];
            #pragma unroll
            for (int mi = 0; mi < 4; mi++) {
                int r = wm*64 + mi*16 + arow;
                int c = 2*ks + asel;
                uint32_t off = (uint32_t)(r*64 + ((c ^ ((r>>1)&3))*16));
                ldsm4(st + off, af[mi][0], af[mi][1], af[mi][2], af[mi][3]);
            }
            uint32_t wh[2][4], wl[2][4];
            #pragma unroll
            for (int np = 0; np < 2; np++) {
                int r = wn*32 + np*16 + brow;
                int c = 2*ks + bsel;
                uint32_t off = (uint32_t)(r*64 + ((c ^ ((r>>1)&3))*16));
                ldsm4(st + 1*OUT_TB + off, wh[np][0], wh[np][1], wh[np][2], wh[np][3]);
                ldsm4(st + 2*OUT_TB + off, wl[np][0], wl[np][1], wl[np][2], wl[np][3]);
            }
            #pragma unroll
            for (int mi = 0; mi < 4; mi++)
                #pragma unroll
                for (int ni = 0; ni < 4; ni++) {
                    uint32_t b0h = wh[ni>>1][(ni&1)*2], b1h = wh[ni>>1][(ni&1)*2+1];
                    uint32_t b0l = wl[ni>>1][(ni&1)*2], b1l = wl[ni>>1][(ni&1)*2+1];
                    mma16816h(acc[mi][ni], af[mi], b0h, b1h);
                    mma16816h(acc[mi][ni], af[mi], b0l, b1l);
                }
        }
    }
    #undef OISSUE

    const int lrow = lane >> 2;
    const int lcol = (lane & 3)*2;
    const int mrow0 = mt*128 + wm*64;
    const int ncol0 = nt*128 + wn*32;
    #pragma unroll
    for (int mi = 0; mi < 4; mi++)
        #pragma unroll
        for (int ni = 0; ni < 4; ni++) {
            int m0 = mrow0 + mi*16 + lrow;
            int n0 = ncol0 + ni*8 + lcol;
            *(float2*)(C + (size_t)m0*1024 + n0) =
                make_float2(acc[mi][ni][0], acc[mi][ni][1]);
            *(float2*)(C + (size_t)(m0+8)*1024 + n0) =
                make_float2(acc[mi][ni][2], acc[mi][ni][3]);
        }
}

// ------------------------------------------------------------------
// Fused flash attention, all single-fp16 operands, log2-domain softmax.
// smem: Q 16K + 2 stages x 2x16K + bias 8K = 88K.
// ------------------------------------------------------------------
#define T16 16384
#define FS_Q 0
#define FS_ST0 (T16)
#define FS_ST1 (3*T16)
#define FS_BIAS (5*T16)
#define FLASH_SMEM (5*T16 + 8192)

#define SWZ(r, c) ((uint32_t)((r)*128 + (((c) ^ ((r)&7))*16)))

__global__ void __launch_bounds__(256, 1) flash_kernel() {
    extern __shared__ __align__(128) char smem[];
    const uint32_t sb = smem_u32(smem);
    float* bias_all = (float*)(smem + FS_BIAS);   // [8][256]

    const int tid  = threadIdx.x;
    const int w = tid >> 5, lane = tid & 31;
    const int mbase = blockIdx.x * 128;
    const int bh = blockIdx.y;
    const int b = bh >> 4, h = bh & 15;

    const size_t base = (size_t)bh*SS*DKK;
    const __nv_bfloat16* Qf = g_qkv + base + (size_t)mbase*DKK;    // fp16, log2-scaled
    const __nv_bfloat16* Kf = g_qkv + 4194304 + base;              // fp16
    const __nv_bfloat16* Vf = g_qkv + 8388608 + base;              // fp16

    #pragma unroll
    for (int i = 0; i < 4; i++) {
        int id = tid + i*256;
        int r = id >> 3, c = id & 7;
        CP_ASYNC16(sb + FS_Q + SWZ(r, c), Qf + (size_t)r*64 + c*8);
    }
    #define ISSUE_KV(j, stoff) do { \
        const size_t _jo = (size_t)(j)*128*64; \
        _Pragma("unroll") \
        for (int _i = 0; _i < 4; _i++) { \
            int _id = tid + _i*256; \
            int _r = _id >> 3, _c = _id & 7; \
            uint32_t _off = SWZ(_r, _c); \
            const size_t _go = _jo + (size_t)_r*64 + _c*8; \
            CP_ASYNC16(sb + (stoff) + 0*T16 + _off, Kf + _go); \
            CP_ASYNC16(sb + (stoff) + 1*T16 + _off, Vf + _go); \
        } \
    } while (0)
    ISSUE_KV(0, FS_ST0); CP_COMMIT();
    ISSUE_KV(1, FS_ST1); CP_COMMIT();

    // preload ALL bias windows while cp.async is in flight
    for (int t = tid; t < 8*255; t += 256) {
        int jj = t / 255;
        int tt = t - jj*255;
        bias_all[jj*256 + tt] =
            g_bias[(size_t)(jj*128 - mbase + tt - 127 + (SS-1))*HH + h];
    }

    float Oacc[8][4];
    #pragma unroll
    for (int d = 0; d < 8; d++)
        #pragma unroll
        for (int q = 0; q < 4; q++) Oacc[d][q] = 0.f;
    float mrun0 = -1e30f, mrun1 = -1e30f, lrun0 = 0.f, lrun1 = 0.f;

    const int r0 = lane >> 2;
    const int colb = (lane & 3)*2;
    const int rl0 = w*16 + r0;
    const int rl1 = rl0 + 8;

    const int a_r = w*16 + (lane & 15);
    const int a_s = lane >> 4;
    const int b_r = ((lane >> 4) << 3) | (lane & 7);
    const int b_s = (lane >> 3) & 1;
    const int v_k = ((lane >> 3) & 1)*8 + (lane & 7);
    const int v_c = lane >> 4;

    CP_WAIT1();
    __syncthreads();
    uint32_t qf[4][4];
    #pragma unroll
    for (int ks = 0; ks < 4; ks++) {
        uint32_t aoff = SWZ(a_r, 2*ks + a_s);
        ldsm4(sb + FS_Q + aoff, qf[ks][0], qf[ks][1], qf[ks][2], qf[ks][3]);
    }

    for (int j = 0; j < 8; j++) {
        if (j > 0) {
            if (j < 7) { CP_WAIT1(); } else { CP_WAIT0(); }
            __syncthreads();
        }

        const uint32_t st = sb + ((j & 1) ? FS_ST1 : FS_ST0);
        const float* bias_s = bias_all + j*256;

        // ---- S = Q K^T (fp16 single) ----
        float sacc[16][4];
        #pragma unroll
        for (int nt = 0; nt < 16; nt++)
            #pragma unroll
            for (int q = 0; q < 4; q++) sacc[nt][q] = 0.f;

        #pragma unroll
        for (int ks = 0; ks < 4; ks++) {
            #pragma unroll
            for (int np = 0; np < 8; np++) {
                uint32_t kh[4];
                uint32_t boff = SWZ(np*16 + b_r, 2*ks + b_s);
                ldsm4(st + 0*T16 + boff, kh[0], kh[1], kh[2], kh[3]);
                mma16816h(sacc[2*np],   qf[ks], kh[0], kh[1]);
                mma16816h(sacc[2*np+1], qf[ks], kh[2], kh[3]);
            }
        }

        // ---- bias (log2 domain) ----
        #pragma unroll
        for (int nt = 0; nt < 16; nt++) {
            int col = nt*8 + colb;
            sacc[nt][0] += bias_s[col     - rl0 + 127];
            sacc[nt][1] += bias_s[col + 1 - rl0 + 127];
            sacc[nt][2] += bias_s[col     - rl1 + 127];
            sacc[nt][3] += bias_s[col + 1 - rl1 + 127];
        }

        // ---- online softmax (base 2) ----
        float mx0 = -1e30f, mx1 = -1e30f;
        #pragma unroll
        for (int nt = 0; nt < 16; nt++) {
            mx0 = fmaxf(mx0, fmaxf(sacc[nt][0], sacc[nt][1]));
            mx1 = fmaxf(mx1, fmaxf(sacc[nt][2], sacc[nt][3]));
        }
        mx0 = fmaxf(mx0, __shfl_xor_sync(0xffffffffu, mx0, 1));
        mx0 = fmaxf(mx0, __shfl_xor_sync(0xffffffffu, mx0, 2));
        mx1 = fmaxf(mx1, __shfl_xor_sync(0xffffffffu, mx1, 1));
        mx1 = fmaxf(mx1, __shfl_xor_sync(0xffffffffu, mx1, 2));

        float mn0 = fmaxf(mrun0, mx0);
        float mn1 = fmaxf(mrun1, mx1);
        float al0 = fast_exp2(mrun0 - mn0);
        float al1 = fast_exp2(mrun1 - mn1);
        mrun0 = mn0; mrun1 = mn1;

        float rs0 = 0.f, rs1 = 0.f;
        #pragma unroll
        for (int nt = 0; nt < 16; nt++) {
            sacc[nt][0] = fast_exp2(sacc[nt][0] - mn0);
            sacc[nt][1] = fast_exp2(sacc[nt][1] - mn0);
            sacc[nt][2] = fast_exp2(sacc[nt][2] - mn1);
            sacc[nt][3] = fast_exp2(sacc[nt][3] - mn1);
            rs0 += sacc[nt][0] + sacc[nt][1];
            rs1 += sacc[nt][2] + sacc[nt][3];
        }
        rs0 += __shfl_xor_sync(0xffffffffu, rs0, 1);
        rs0 += __shfl_xor_sync(0xffffffffu, rs0, 2);
        rs1 += __shfl_xor_sync(0xffffffffu, rs1, 1);
        rs1 += __shfl_xor_sync(0xffffffffu, rs1, 2);
        lrun0 = lrun0*al0 + rs0;
        lrun1 = lrun1*al1 + rs1;

        #pragma unroll
        for (int d = 0; d < 8; d++) {
            Oacc[d][0] *= al0; Oacc[d][1] *= al0;
            Oacc[d][2] *= al1; Oacc[d][3] *= al1;
        }

        // ---- O += P V (fp16 single both) ----
        #pragma unroll
        for (int ks = 0; ks < 8; ks++) {
            uint32_t ph[4];
            {
                __half2 t0 = __floats2half2_rn(sacc[2*ks][0],   sacc[2*ks][1]);
                __half2 t1 = __floats2half2_rn(sacc[2*ks][2],   sacc[2*ks][3]);
                __half2 t2 = __floats2half2_rn(sacc[2*ks+1][0], sacc[2*ks+1][1]);
                __half2 t3 = __floats2half2_rn(sacc[2*ks+1][2], sacc[2*ks+1][3]);
                ph[0] = *(uint32_t*)&t0;
                ph[1] = *(uint32_t*)&t1;
                ph[2] = *(uint32_t*)&t2;
                ph[3] = *(uint32_t*)&t3;
            }
            #pragma unroll
            for (int dp = 0; dp < 4; dp++) {
                uint32_t vh[4];
                uint32_t voff = SWZ(ks*16 + v_k, dp*2 + v_c);
                ldsm4t(st + 1*T16 + voff, vh[0], vh[1], vh[2], vh[3]);
                mma16816h(Oacc[2*dp],   ph, vh[0], vh[1]);
                mma16816h(Oacc[2*dp+1], ph, vh[2], vh[3]);
            }
        }

        __syncthreads();
        if (j + 2 < 8) {
            ISSUE_KV(j + 2, ((j & 1) ? FS_ST1 : FS_ST0));
            CP_COMMIT();
        }
    }
    #undef ISSUE_KV

    // ---- epilogue: normalize + write ctx as single fp16 ----
    float inv0 = 1.0f / lrun0;
    float inv1 = 1.0f / lrun1;
    int m0 = mbase + rl0;
    int m1 = mbase + rl1;
    #pragma unroll
    for (int dt = 0; dt < 8; dt++) {
        int d = dt*8 + colb;
        size_t i0 = ((size_t)(b*SS + m0))*DD + h*DKK + d;
        size_t i1 = ((size_t)(b*SS + m1))*DD + h*DKK + d;
        __half2 h0 = __floats2half2_rn(Oacc[dt][0]*inv0, Oacc[dt][1]*inv0);
        *(uint32_t*)&g_ctx[i0] = *(uint32_t*)&h0;
        __half2 h1 = __floats2half2_rn(Oacc[dt][2]*inv1, Oacc[dt][3]*inv1);
        *(uint32_t*)&g_ctx[i1] = *(uint32_t*)&h1;
    }
}

// ------------------------------------------------------------------
extern "C" void kernel_launch(void* const* d_in, const int* in_sizes, int n_in,
                              void* d_out, int out_size) {
    const float* hidden   = (const float*)d_in[0];
    const float* Wq       = (const float*)d_in[1];
    const float* Wk       = (const float*)d_in[2];
    const float* Wv       = (const float*)d_in[3];
    const float* Wo       = (const float*)d_in[4];
    const float* rel_bias = (const float*)d_in[5];
    float* out = (float*)d_out;

    __nv_bfloat16 *pahi, *palo, *pwhi, *pwlo, *pctx;
    cudaGetSymbolAddress((void**)&pahi, g_ahi);
    cudaGetSymbolAddress((void**)&palo, g_alo);
    cudaGetSymbolAddress((void**)&pwhi, g_whi);
    cudaGetSymbolAddress((void**)&pwlo, g_wlo);
    cudaGetSymbolAddress((void**)&pctx, g_ctx);

    cudaFuncSetAttribute(gemm_qkv_kernel,
                         cudaFuncAttributeMaxDynamicSharedMemorySize, GEMM_SMEM);
    cudaFuncSetAttribute(gemm_out_kernel,
                         cudaFuncAttributeMaxDynamicSharedMemorySize, OUT_SMEM);
    cudaFuncSetAttribute(flash_kernel,
                         cudaFuncAttributeMaxDynamicSharedMemorySize, FLASH_SMEM);

    bias_kernel<<<((2*SS-1)*HH + 255)/256, 256>>>(rel_bias);
    split_all_kernel<<<(8388608 + 255)/256, 256>>>(
        hidden, Wq, Wk, Wv, Wo, pahi, palo, pwhi, pwlo);

    // fused QKV projection -> Q (log2-scaled), K, V single fp16
    gemm_qkv_kernel<<<dim3(24, 32), 256, GEMM_SMEM>>>(
        pahi, palo, pwhi, pwlo, nullptr);

    // fused attention
    flash_kernel<<<dim3(8, BH), 256, FLASH_SMEM>>>();

    // output projection: ctx_f16 x Wo_f16(hi+lo) -> fp32 out
    gemm_out_kernel<<<dim3(8, 32), 256, OUT_SMEM>>>(
        pctx, pwhi + 3145728, pwlo + 3145728, out);
}

// round 16
// speedup vs baseline: 2.3344x; 1.1660x over previous
#include <cuda_runtime.h>
#include <cuda_bf16.h>
#include <cuda_fp16.h>
#include <math.h>
#include <stdint.h>

#define BB 4
#define SS 1024
#define DD 1024
#define HH 16
#define DKK 64
#define BH (BB*HH)

// ---- scratch (device globals; no allocation allowed) ----
__device__ float g_bias[(2*SS-1)*HH];          // pre-scaled by log2(e)

__device__ __align__(16) __nv_bfloat16 g_abh[4096*1024];  // hidden bf16 hi
__device__ __align__(16) __nv_bfloat16 g_abl[4096*1024];  // hidden bf16 lo
__device__ __align__(16) __nv_bfloat16 g_afh[4096*1024];  // hidden fp16 hi (bits)
__device__ __align__(16) __nv_bfloat16 g_afl[4096*1024];  // hidden fp16 lo (bits)
// W storage: rows 0..1M: Wq bf16 hi(whi)/lo(wlo); whi rows 1M..2M Wk f16,
// 2M..3M Wv f16, 3M..4M Wo f16 (wlo unused there)
__device__ __align__(16) __nv_bfloat16 g_whi[4096*1024];
__device__ __align__(16) __nv_bfloat16 g_wlo[4096*1024];
// q|k|v all single fp16 (q pre-scaled by log2e)  [t][bh][s][dk]
__device__ __align__(16) __nv_bfloat16 g_qkv[3*4194304];
__device__ __align__(16) __nv_bfloat16 g_ctx[4096*1024];  // ctx fp16 [b*s][h*dk]

// ================= PTX helpers (baseline ISA only) =================
__device__ __forceinline__ uint32_t smem_u32(const void* p) {
    uint32_t a;
    asm("{ .reg .u64 t; cvta.to.shared.u64 t, %1; cvt.u32.u64 %0, t; }"
        : "=r"(a) : "l"(p));
    return a;
}

#define CP_ASYNC16(sa, ga) \
    asm volatile("cp.async.cg.shared.global [%0], [%1], 16;" \
        :: "r"(sa), "l"(ga) : "memory")
#define CP_COMMIT() asm volatile("cp.async.commit_group;" ::: "memory")
#define CP_WAIT1()  asm volatile("cp.async.wait_group 1;" ::: "memory")
#define CP_WAIT0()  asm volatile("cp.async.wait_group 0;" ::: "memory")

__device__ __forceinline__ void ldsm4(uint32_t addr, uint32_t& r0, uint32_t& r1,
                                      uint32_t& r2, uint32_t& r3) {
    asm volatile("ldmatrix.sync.aligned.m8n8.x4.shared.b16 {%0,%1,%2,%3}, [%4];"
        : "=r"(r0), "=r"(r1), "=r"(r2), "=r"(r3) : "r"(addr));
}
__device__ __forceinline__ void ldsm4t(uint32_t addr, uint32_t& r0, uint32_t& r1,
                                       uint32_t& r2, uint32_t& r3) {
    asm volatile("ldmatrix.sync.aligned.m8n8.x4.trans.shared.b16 {%0,%1,%2,%3}, [%4];"
        : "=r"(r0), "=r"(r1), "=r"(r2), "=r"(r3) : "r"(addr));
}

__device__ __forceinline__ void mma16816(float* d, const uint32_t* a,
                                         uint32_t b0, uint32_t b1) {
    asm volatile("mma.sync.aligned.m16n8k16.row.col.f32.bf16.bf16.f32 "
        "{%0,%1,%2,%3}, {%4,%5,%6,%7}, {%8,%9}, {%0,%1,%2,%3};"
        : "+f"(d[0]), "+f"(d[1]), "+f"(d[2]), "+f"(d[3])
        : "r"(a[0]), "r"(a[1]), "r"(a[2]), "r"(a[3]), "r"(b0), "r"(b1));
}
__device__ __forceinline__ void mma16816h(float* d, const uint32_t* a,
                                          uint32_t b0, uint32_t b1) {
    asm volatile("mma.sync.aligned.m16n8k16.row.col.f32.f16.f16.f32 "
        "{%0,%1,%2,%3}, {%4,%5,%6,%7}, {%8,%9}, {%0,%1,%2,%3};"
        : "+f"(d[0]), "+f"(d[1]), "+f"(d[2]), "+f"(d[3])
        : "r"(a[0]), "r"(a[1]), "r"(a[2]), "r"(a[3]), "r"(b0), "r"(b1));
}

__device__ __forceinline__ float fast_exp2(float x) {
    float r;
    asm("ex2.approx.f32 %0, %1;" : "=f"(r) : "f"(x));
    return r;
}

// ------------------------------------------------------------------
// splits: hidden -> bf16 hi/lo AND fp16 hi/lo; Wq bf16 hi/lo; Wk/Wv/Wo fp16.
// ------------------------------------------------------------------
__global__ void split_all_kernel(const float* __restrict__ hid,
                                 const float* __restrict__ w0, const float* __restrict__ w1,
                                 const float* __restrict__ w2, const float* __restrict__ w3,
                                 __nv_bfloat16* __restrict__ abh, __nv_bfloat16* __restrict__ abl,
                                 __nv_bfloat16* __restrict__ afh, __nv_bfloat16* __restrict__ afl,
                                 __nv_bfloat16* __restrict__ whi, __nv_bfloat16* __restrict__ wlo) {
    int i = blockIdx.x * blockDim.x + threadIdx.x;   // 0..8M-1
    if (i < 4194304) {
        float v = hid[i];
        __nv_bfloat16 hb = __float2bfloat16(v);
        abh[i] = hb;
        abl[i] = __float2bfloat16(v - __bfloat162float(hb));
        __half hf = __float2half_rn(v);
        *(__half*)&afh[i] = hf;
        *(__half*)&afl[i] = __float2half_rn(v - __half2float(hf));
    } else {
        int j = i - 4194304;
        int t = j >> 20;
        int off = j & 1048575;
        const float* src = (t == 0) ? w0 : (t == 1) ? w1 : (t == 2) ? w2 : w3;
        float v = src[off];
        if (t == 0) {   // Wq: bf16 hi/lo
            __nv_bfloat16 h = __float2bfloat16(v);
            whi[j] = h;
            wlo[j] = __float2bfloat16(v - __bfloat162float(h));
        } else {        // Wk, Wv, Wo: fp16 single
            *(__half*)&whi[j] = __float2half_rn(v);
        }
    }
}

// ------------------------------------------------------------------
__global__ void bias_kernel(const float* __restrict__ rel_bias) {
    int idx = blockIdx.x * blockDim.x + threadIdx.x;
    const int total = (2*SS-1)*HH;
    if (idx >= total) return;
    int d = idx / HH;
    int h = idx - d*HH;
    int rp = d - (SS - 1);
    int rb = (rp > 0) ? 16 : 0;
    int n = rp < 0 ? -rp : rp;
    int b;
    if (n < 8) {
        b = n;
    } else {
        double v = log((double)n / 8.0) / log(16.0) * 8.0;
        int large = 8 + (int)v;
        b = large < 15 ? large : 15;
    }
    g_bias[idx] = (float)((double)rel_bias[(rb + b)*HH + h] * 1.4426950408889634);
}

// ------------------------------------------------------------------
// QKV GEMM. t = nt>>3: t==0 Q via bf16x3; t==1,2 K,V via fp16x2
// (A fp16 hi/lo x W fp16 single). Outputs single fp16 head-split
// (Q scaled by log2e).
// ------------------------------------------------------------------
#define BKG 32
#define STAGES 3
#define TENSOR_BYTES (128*64)
#define STAGE_BYTES  (4*TENSOR_BYTES)
#define GEMM_SMEM    (STAGES*STAGE_BYTES)

__global__ void __launch_bounds__(256, 2) gemm_qkv_kernel(
    const __nv_bfloat16* __restrict__ Abh, const __nv_bfloat16* __restrict__ Abl,
    const __nv_bfloat16* __restrict__ Afh, const __nv_bfloat16* __restrict__ Afl,
    const __nv_bfloat16* __restrict__ Whi, const __nv_bfloat16* __restrict__ Wlo)
{
    extern __shared__ __align__(128) char smem[];
    const uint32_t sb = smem_u32(smem);
    const int tid  = threadIdx.x;
    const int warp = tid >> 5, lane = tid & 31;
    const int wm = warp >> 2, wn = warp & 3;
    const int nt = blockIdx.x, mt = blockIdx.y;
    const int t  = nt >> 3;

    const __nv_bfloat16* src0 = ((t == 0) ? Abh : Afh) + (size_t)(mt*128)*1024;
    const __nv_bfloat16* src1 = ((t == 0) ? Abl : Afl) + (size_t)(mt*128)*1024;
    const __nv_bfloat16* src2 = Whi + (size_t)(nt*128)*1024;
    const __nv_bfloat16* src3 = Wlo + (size_t)(nt*128)*1024;   // used only t==0
    const __nv_bfloat16* mysrc = (tid < 64) ? src0 : (tid < 128) ? src1
                               : (tid < 192) ? src2 : src3;
    const int t4 = tid >> 6;
    const int li = tid & 63;
    const bool active = (t == 0) || (t4 < 3);

    #define ISSUE(it) do { \
        if (active) { \
            int _stg = (it) % STAGES; \
            uint32_t _sbase = sb + _stg*STAGE_BYTES + t4*TENSOR_BYTES; \
            const __nv_bfloat16* _g = mysrc + (it)*BKG; \
            _Pragma("unroll") \
            for (int _j = 0; _j < 8; _j++) { \
                int _ch = li + _j*64; \
                int _r = _ch >> 2, _c = _ch & 3; \
                int _cs = _c ^ ((_r >> 1) & 3); \
                CP_ASYNC16(_sbase + _r*64 + _cs*16, _g + (size_t)_r*1024 + _c*8); \
            } \
        } \
    } while (0)

    ISSUE(0); CP_COMMIT();
    ISSUE(1); CP_COMMIT();

    float acc[4][4][4];
    #pragma unroll
    for (int i = 0; i < 4; i++)
        #pragma unroll
        for (int j = 0; j < 4; j++)
            #pragma unroll
            for (int q = 0; q < 4; q++) acc[i][j][q] = 0.f;

    const int arow = lane & 15;
    const int asel = lane >> 4;
    const int brow = ((lane >> 4) << 3) | (lane & 7);
    const int bsel = (lane >> 3) & 1;

    for (int it = 0; it < 32; it++) {
        CP_WAIT1();
        __syncthreads();
        if (it + 2 < 32) ISSUE(it + 2);
        CP_COMMIT();

        const uint32_t st = sb + (it % STAGES)*STAGE_BYTES;
        #pragma unroll
        for (int ks = 0; ks < 2; ks++) {
            uint32_t ah[4][4], al[4][4];
            #pragma unroll
            for (int mi = 0; mi < 4; mi++) {
                int r = wm*64 + mi*16 + arow;
                int c = 2*ks + asel;
                uint32_t off = (uint32_t)(r*64 + ((c ^ ((r>>1)&3))*16));
                ldsm4(st + off,               ah[mi][0], ah[mi][1], ah[mi][2], ah[mi][3]);
                ldsm4(st + TENSOR_BYTES + off, al[mi][0], al[mi][1], al[mi][2], al[mi][3]);
            }
            if (t == 0) {
                uint32_t bh2[2][4], bl2[2][4];
                #pragma unroll
                for (int np = 0; np < 2; np++) {
                    int r = wn*32 + np*16 + brow;
                    int c = 2*ks + bsel;
                    uint32_t off = (uint32_t)(r*64 + ((c ^ ((r>>1)&3))*16));
                    ldsm4(st + 2*TENSOR_BYTES + off, bh2[np][0], bh2[np][1], bh2[np][2], bh2[np][3]);
                    ldsm4(st + 3*TENSOR_BYTES + off, bl2[np][0], bl2[np][1], bl2[np][2], bl2[np][3]);
                }
                #pragma unroll
                for (int mi = 0; mi < 4; mi++)
                    #pragma unroll
                    for (int ni = 0; ni < 4; ni++) {
                        uint32_t b0h = bh2[ni>>1][(ni&1)*2], b1h = bh2[ni>>1][(ni&1)*2+1];
                        uint32_t b0l = bl2[ni>>1][(ni&1)*2], b1l = bl2[ni>>1][(ni&1)*2+1];
                        mma16816(acc[mi][ni], ah[mi], b0h, b1h);
                        mma16816(acc[mi][ni], ah[mi], b0l, b1l);
                        mma16816(acc[mi][ni], al[mi], b0h, b1h);
                    }
            } else {
                uint32_t wf[2][4];
                #pragma unroll
                for (int np = 0; np < 2; np++) {
                    int r = wn*32 + np*16 + brow;
                    int c = 2*ks + bsel;
                    uint32_t off = (uint32_t)(r*64 + ((c ^ ((r>>1)&3))*16));
                    ldsm4(st + 2*TENSOR_BYTES + off, wf[np][0], wf[np][1], wf[np][2], wf[np][3]);
                }
                #pragma unroll
                for (int mi = 0; mi < 4; mi++)
                    #pragma unroll
                    for (int ni = 0; ni < 4; ni++) {
                        uint32_t b0 = wf[ni>>1][(ni&1)*2], b1 = wf[ni>>1][(ni&1)*2+1];
                        mma16816h(acc[mi][ni], ah[mi], b0, b1);
                        mma16816h(acc[mi][ni], al[mi], b0, b1);
                    }
            }
        }
    }
    #undef ISSUE

    const int lrow = lane >> 2;
    const int lcol = (lane & 3)*2;
    const float scl = (t == 0) ? 1.44269504f : 1.0f;   // Q in log2 domain
    const size_t tbase = (size_t)t * 4194304;
    const int mrow0 = mt*128 + wm*64;
    const int ncol0 = (nt & 7)*128 + wn*32;
    #pragma unroll
    for (int mi = 0; mi < 4; mi++)
        #pragma unroll
        for (int ni = 0; ni < 4; ni++) {
            int m0 = mrow0 + mi*16 + lrow;
            int m1 = m0 + 8;
            int n0 = ncol0 + ni*8 + lcol;
            int h = n0 >> 6, dk = n0 & 63;
            int b0 = m0 >> 10, s0 = m0 & 1023;
            int b1 = m1 >> 10, s1 = m1 & 1023;
            size_t i0 = tbase + ((size_t)((b0*HH + h)*SS + s0))*DKK + dk;
            size_t i1 = tbase + ((size_t)((b1*HH + h)*SS + s1))*DKK + dk;
            __half2 h0 = __floats2half2_rn(acc[mi][ni][0]*scl, acc[mi][ni][1]*scl);
            *(uint32_t*)&g_qkv[i0] = *(uint32_t*)&h0;
            __half2 h1 = __floats2half2_rn(acc[mi][ni][2]*scl, acc[mi][ni][3]*scl);
            *(uint32_t*)&g_qkv[i1] = *(uint32_t*)&h1;
        }
}

// ------------------------------------------------------------------
// Out projection: single fp16 x single fp16, 1 MMA.
// ------------------------------------------------------------------
#define OUT_TB 8192
#define OUT_STAGE (2*OUT_TB)
#define OUT_SMEM (STAGES*OUT_STAGE)

__global__ void __launch_bounds__(256, 2) gemm_out_kernel(
    const __nv_bfloat16* __restrict__ Af,    // ctx fp16 bits
    const __nv_bfloat16* __restrict__ Wf,    // Wo fp16 bits
    float* __restrict__ C)
{
    extern __shared__ __align__(128) char smem[];
    const uint32_t sb = smem_u32(smem);
    const int tid  = threadIdx.x;
    const int warp = tid >> 5, lane = tid & 31;
    const int wm = warp >> 2, wn = warp & 3;
    const int nt = blockIdx.x, mt = blockIdx.y;

    const __nv_bfloat16* srcA = Af + (size_t)(mt*128)*1024;
    const __nv_bfloat16* srcW = Wf + (size_t)(nt*128)*1024;

    #define OISSUE(it) do { \
        int _stg = (it) % STAGES; \
        uint32_t _sbase = sb + _stg*OUT_STAGE; \
        _Pragma("unroll") \
        for (int _k = 0; _k < 4; _k++) { \
            int _c0 = tid + _k*256; \
            int _t = _c0 >> 9; \
            int _idx = _c0 & 511; \
            int _r = _idx >> 2, _cc = _idx & 3; \
            int _cs = _cc ^ ((_r >> 1) & 3); \
            const __nv_bfloat16* _g = ((_t == 0) ? srcA : srcW) + (it)*BKG; \
            CP_ASYNC16(_sbase + _t*OUT_TB + _r*64 + _cs*16, \
                       _g + (size_t)_r*1024 + _cc*8); \
        } \
    } while (0)

    OISSUE(0); CP_COMMIT();
    OISSUE(1); CP_COMMIT();

    float acc[4][4][4];
    #pragma unroll
    for (int i = 0; i < 4; i++)
        #pragma unroll
        for (int j = 0; j < 4; j++)
            #pragma unroll
            for (int q = 0; q < 4; q++) acc[i][j][q] = 0.f;

    const int arow = lane & 15;
    const int asel = lane >> 4;
    const int brow = ((lane >> 4) << 3) | (lane & 7);
    const int bsel = (lane >> 3) & 1;

    for (int it = 0; it < 32; it++) {
        CP_WAIT1();
        __syncthreads();
        if (it + 2 < 32) OISSUE(it + 2);
        CP_COMMIT();

        const uint32_t st = sb + (it % STAGES)*OUT_STAGE;
        #pragma unroll
        for (int ks = 0; ks < 2; ks++) {
            uint32_t af[4][4];
            #pragma unroll
            for (int mi = 0; mi < 4; mi++) {
                int r = wm*64 + mi*16 + arow;
                int c = 2*ks + asel;
                uint32_t off = (uint32_t)(r*64 + ((c ^ ((r>>1)&3))*16));
                ldsm4(st + off, af[mi][0], af[mi][1], af[mi][2], af[mi][3]);
            }
            uint32_t wf[2][4];
            #pragma unroll
            for (int np = 0; np < 2; np++) {
                int r = wn*32 + np*16 + brow;
                int c = 2*ks + bsel;
                uint32_t off = (uint32_t)(r*64 + ((c ^ ((r>>1)&3))*16));
                ldsm4(st + OUT_TB + off, wf[np][0], wf[np][1], wf[np][2], wf[np][3]);
            }
            #pragma unroll
            for (int mi = 0; mi < 4; mi++)
                #pragma unroll
                for (int ni = 0; ni < 4; ni++) {
                    uint32_t b0 = wf[ni>>1][(ni&1)*2], b1 = wf[ni>>1][(ni&1)*2+1];
                    mma16816h(acc[mi][ni], af[mi], b0, b1);
                }
        }
    }
    #undef OISSUE

    const int lrow = lane >> 2;
    const int lcol = (lane & 3)*2;
    const int mrow0 = mt*128 + wm*64;
    const int ncol0 = nt*128 + wn*32;
    #pragma unroll
    for (int mi = 0; mi < 4; mi++)
        #pragma unroll
        for (int ni = 0; ni < 4; ni++) {
            int m0 = mrow0 + mi*16 + lrow;
            int n0 = ncol0 + ni*8 + lcol;
            *(float2*)(C + (size_t)m0*1024 + n0) =
                make_float2(acc[mi][ni][0], acc[mi][ni][1]);
            *(float2*)(C + (size_t)(m0+8)*1024 + n0) =
                make_float2(acc[mi][ni][2], acc[mi][ni][3]);
        }
}

// ------------------------------------------------------------------
// Fused flash attention, single-fp16 operands, log2-domain softmax.
// sacc initialized from bias; row-sum via ones-B MMA (no shuffle).
// ------------------------------------------------------------------
#define T16 16384
#define FS_Q 0
#define FS_ST0 (T16)
#define FS_ST1 (3*T16)
#define FS_BIAS (5*T16)
#define FLASH_SMEM (5*T16 + 8192)

#define SWZ(r, c) ((uint32_t)((r)*128 + (((c) ^ ((r)&7))*16)))
#define HONES 0x3C003C00u

__global__ void __launch_bounds__(256, 1) flash_kernel() {
    extern __shared__ __align__(128) char smem[];
    const uint32_t sb = smem_u32(smem);
    float* bias_all = (float*)(smem + FS_BIAS);   // [8][256]

    const int tid  = threadIdx.x;
    const int w = tid >> 5, lane = tid & 31;
    const int mbase = blockIdx.x * 128;
    const int bh = blockIdx.y;
    const int b = bh >> 4, h = bh & 15;

    const size_t base = (size_t)bh*SS*DKK;
    const __nv_bfloat16* Qf = g_qkv + base + (size_t)mbase*DKK;    // fp16, log2-scaled
    const __nv_bfloat16* Kf = g_qkv + 4194304 + base;              // fp16
    const __nv_bfloat16* Vf = g_qkv + 8388608 + base;              // fp16

    #pragma unroll
    for (int i = 0; i < 4; i++) {
        int id = tid + i*256;
        int r = id >> 3, c = id & 7;
        CP_ASYNC16(sb + FS_Q + SWZ(r, c), Qf + (size_t)r*64 + c*8);
    }
    #define ISSUE_KV(j, stoff) do { \
        const size_t _jo = (size_t)(j)*128*64; \
        _Pragma("unroll") \
        for (int _i = 0; _i < 4; _i++) { \
            int _id = tid + _i*256; \
            int _r = _id >> 3, _c = _id & 7; \
            uint32_t _off = SWZ(_r, _c); \
            const size_t _go = _jo + (size_t)_r*64 + _c*8; \
            CP_ASYNC16(sb + (stoff) + 0*T16 + _off, Kf + _go); \
            CP_ASYNC16(sb + (stoff) + 1*T16 + _off, Vf + _go); \
        } \
    } while (0)
    ISSUE_KV(0, FS_ST0); CP_COMMIT();
    ISSUE_KV(1, FS_ST1); CP_COMMIT();

    for (int t = tid; t < 8*255; t += 256) {
        int jj = t / 255;
        int tt = t - jj*255;
        bias_all[jj*256 + tt] =
            g_bias[(size_t)(jj*128 - mbase + tt - 127 + (SS-1))*HH + h];
    }

    float Oacc[8][4];
    #pragma unroll
    for (int d = 0; d < 8; d++)
        #pragma unroll
        for (int q = 0; q < 4; q++) Oacc[d][q] = 0.f;
    float mrun0 = -1e30f, mrun1 = -1e30f, lrun0 = 0.f, lrun1 = 0.f;

    const int r0 = lane >> 2;
    const int colb = (lane & 3)*2;
    const int rl0 = w*16 + r0;
    const int rl1 = rl0 + 8;

    const int a_r = w*16 + (lane & 15);
    const int a_s = lane >> 4;
    const int b_r = ((lane >> 4) << 3) | (lane & 7);
    const int b_s = (lane >> 3) & 1;
    const int v_k = ((lane >> 3) & 1)*8 + (lane & 7);
    const int v_c = lane >> 4;

    CP_WAIT1();
    __syncthreads();
    uint32_t qf[4][4];
    #pragma unroll
    for (int ks = 0; ks < 4; ks++) {
        uint32_t aoff = SWZ(a_r, 2*ks + a_s);
        ldsm4(sb + FS_Q + aoff, qf[ks][0], qf[ks][1], qf[ks][2], qf[ks][3]);
    }

    for (int j = 0; j < 8; j++) {
        if (j > 0) {
            if (j < 7) { CP_WAIT1(); } else { CP_WAIT0(); }
            __syncthreads();
        }

        const uint32_t st = sb + ((j & 1) ? FS_ST1 : FS_ST0);
        const float* bias_s = bias_all + j*256;

        // ---- S = bias + Q K^T : init accumulators from bias ----
        float sacc[16][4];
        #pragma unroll
        for (int nt = 0; nt < 16; nt++) {
            int col = nt*8 + colb;
            sacc[nt][0] = bias_s[col     - rl0 + 127];
            sacc[nt][1] = bias_s[col + 1 - rl0 + 127];
            sacc[nt][2] = bias_s[col     - rl1 + 127];
            sacc[nt][3] = bias_s[col + 1 - rl1 + 127];
        }

        #pragma unroll
        for (int ks = 0; ks < 4; ks++) {
            #pragma unroll
            for (int np = 0; np < 8; np++) {
                uint32_t kh[4];
                uint32_t boff = SWZ(np*16 + b_r, 2*ks + b_s);
                ldsm4(st + 0*T16 + boff, kh[0], kh[1], kh[2], kh[3]);
                mma16816h(sacc[2*np],   qf[ks], kh[0], kh[1]);
                mma16816h(sacc[2*np+1], qf[ks], kh[2], kh[3]);
            }
        }

        // ---- online softmax (base 2) ----
        float mx0 = -1e30f, mx1 = -1e30f;
        #pragma unroll
        for (int nt = 0; nt < 16; nt++) {
            mx0 = fmaxf(mx0, fmaxf(sacc[nt][0], sacc[nt][1]));
            mx1 = fmaxf(mx1, fmaxf(sacc[nt][2], sacc[nt][3]));
        }
        mx0 = fmaxf(mx0, __shfl_xor_sync(0xffffffffu, mx0, 1));
        mx0 = fmaxf(mx0, __shfl_xor_sync(0xffffffffu, mx0, 2));
        mx1 = fmaxf(mx1, __shfl_xor_sync(0xffffffffu, mx1, 1));
        mx1 = fmaxf(mx1, __shfl_xor_sync(0xffffffffu, mx1, 2));

        float mn0 = fmaxf(mrun0, mx0);
        float mn1 = fmaxf(mrun1, mx1);
        float al0 = fast_exp2(mrun0 - mn0);
        float al1 = fast_exp2(mrun1 - mn1);
        mrun0 = mn0; mrun1 = mn1;

        #pragma unroll
        for (int nt = 0; nt < 16; nt++) {
            sacc[nt][0] = fast_exp2(sacc[nt][0] - mn0);
            sacc[nt][1] = fast_exp2(sacc[nt][1] - mn0);
            sacc[nt][2] = fast_exp2(sacc[nt][2] - mn1);
            sacc[nt][3] = fast_exp2(sacc[nt][3] - mn1);
        }

        #pragma unroll
        for (int d = 0; d < 8; d++) {
            Oacc[d][0] *= al0; Oacc[d][1] *= al0;
            Oacc[d][2] *= al1; Oacc[d][3] *= al1;
        }

        // ---- O += P V; row-sum via ones-B MMA ----
        float ones_acc[4] = {0.f, 0.f, 0.f, 0.f};
        #pragma unroll
        for (int ks = 0; ks < 8; ks++) {
            uint32_t ph[4];
            {
                __half2 t0 = __floats2half2_rn(sacc[2*ks][0],   sacc[2*ks][1]);
                __half2 t1 = __floats2half2_rn(sacc[2*ks][2],   sacc[2*ks][3]);
                __half2 t2 = __floats2half2_rn(sacc[2*ks+1][0], sacc[2*ks+1][1]);
                __half2 t3 = __floats2half2_rn(sacc[2*ks+1][2], sacc[2*ks+1][3]);
                ph[0] = *(uint32_t*)&t0;
                ph[1] = *(uint32_t*)&t1;
                ph[2] = *(uint32_t*)&t2;
                ph[3] = *(uint32_t*)&t3;
            }
            mma16816h(ones_acc, ph, HONES, HONES);
            #pragma unroll
            for (int dp = 0; dp < 4; dp++) {
                uint32_t vh[4];
                uint32_t voff = SWZ(ks*16 + v_k, dp*2 + v_c);
                ldsm4t(st + 1*T16 + voff, vh[0], vh[1], vh[2], vh[3]);
                mma16816h(Oacc[2*dp],   ph, vh[0], vh[1]);
                mma16816h(Oacc[2*dp+1], ph, vh[2], vh[3]);
            }
        }
        lrun0 = lrun0*al0 + ones_acc[0];
        lrun1 = lrun1*al1 + ones_acc[2];

        __syncthreads();
        if (j + 2 < 8) {
            ISSUE_KV(j + 2, ((j & 1) ? FS_ST1 : FS_ST0));
            CP_COMMIT();
        }
    }
    #undef ISSUE_KV

    // ---- epilogue: normalize + write ctx as single fp16 ----
    float inv0 = 1.0f / lrun0;
    float inv1 = 1.0f / lrun1;
    int m0 = mbase + rl0;
    int m1 = mbase + rl1;
    #pragma unroll
    for (int dt = 0; dt < 8; dt++) {
        int d = dt*8 + colb;
        size_t i0 = ((size_t)(b*SS + m0))*DD + h*DKK + d;
        size_t i1 = ((size_t)(b*SS + m1))*DD + h*DKK + d;
        __half2 h0 = __floats2half2_rn(Oacc[dt][0]*inv0, Oacc[dt][1]*inv0);
        *(uint32_t*)&g_ctx[i0] = *(uint32_t*)&h0;
        __half2 h1 = __floats2half2_rn(Oacc[dt][2]*inv1, Oacc[dt][3]*inv1);
        *(uint32_t*)&g_ctx[i1] = *(uint32_t*)&h1;
    }
}

// ------------------------------------------------------------------
extern "C" void kernel_launch(void* const* d_in, const int* in_sizes, int n_in,
                              void* d_out, int out_size) {
    const float* hidden   = (const float*)d_in[0];
    const float* Wq       = (const float*)d_in[1];
    const float* Wk       = (const float*)d_in[2];
    const float* Wv       = (const float*)d_in[3];
    const float* Wo       = (const float*)d_in[4];
    const float* rel_bias = (const float*)d_in[5];
    float* out = (float*)d_out;

    __nv_bfloat16 *pabh, *pabl, *pafh, *pafl, *pwhi, *pwlo, *pctx;
    cudaGetSymbolAddress((void**)&pabh, g_abh);
    cudaGetSymbolAddress((void**)&pabl, g_abl);
    cudaGetSymbolAddress((void**)&pafh, g_afh);
    cudaGetSymbolAddress((void**)&pafl, g_afl);
    cudaGetSymbolAddress((void**)&pwhi, g_whi);
    cudaGetSymbolAddress((void**)&pwlo, g_wlo);
    cudaGetSymbolAddress((void**)&pctx, g_ctx);

    cudaFuncSetAttribute(gemm_qkv_kernel,
                         cudaFuncAttributeMaxDynamicSharedMemorySize, GEMM_SMEM);
    cudaFuncSetAttribute(gemm_out_kernel,
                         cudaFuncAttributeMaxDynamicSharedMemorySize, OUT_SMEM);
    cudaFuncSetAttribute(flash_kernel,
                         cudaFuncAttributeMaxDynamicSharedMemorySize, FLASH_SMEM);

    bias_kernel<<<((2*SS-1)*HH + 255)/256, 256>>>(rel_bias);
    split_all_kernel<<<(8388608 + 255)/256, 256>>>(
        hidden, Wq, Wk, Wv, Wo, pabh, pabl, pafh, pafl, pwhi, pwlo);

    // QKV: Q bf16x3, K/V fp16x2 -> single fp16 head-split
    gemm_qkv_kernel<<<dim3(24, 32), 256, GEMM_SMEM>>>(
        pabh, pabl, pafh, pafl, pwhi, pwlo);

    // fused attention
    flash_kernel<<<dim3(8, BH), 256, FLASH_SMEM>>>();

    // output projection: ctx_f16 x Wo_f16 -> fp32 (1 MMA)
    gemm_out_kernel<<<dim3(8, 32), 256, OUT_SMEM>>>(
        pctx, pwhi + 3145728, out);
}